// round 8
// baseline (speedup 1.0000x reference)
#include <cuda_runtime.h>
#include <math.h>
#include <stdint.h>

#define Bv 4
#define Lv 4096
#define Dv 512
#define Pv 128
#define Vv 8
#define Mv (Bv*Lv)          // 16384
#define NCv 64
#define NC_SH 6
#define NC_MASK 63
#define LCv (Lv/NCv)        // 64
#define PI_F 3.14159265358979323846f
#define INV_SQRT_D 0.044194173824159216f
#define INV_SQRT_P 0.08838834764831845f

// ================= helpers =================
__device__ __forceinline__ uint32_t smem_u32(const void* p) {
    uint32_t a;
    asm("{ .reg .u64 t; cvta.to.shared.u64 t, %1; cvt.u32.u64 %0, t; }" : "=r"(a) : "l"(p));
    return a;
}
__device__ __forceinline__ void cp16(uint32_t s, const void* g) {
    asm volatile("cp.async.cg.shared.global [%0], [%1], 16;" :: "r"(s), "l"(g) : "memory");
}
#define CP_COMMIT() asm volatile("cp.async.commit_group;" ::: "memory")
#define CP_WAIT1()  asm volatile("cp.async.wait_group 1;" ::: "memory")
#define CP_WAIT0()  asm volatile("cp.async.wait_group 0;" ::: "memory")

__device__ __forceinline__ float f2tf32f(float v) {
    uint32_t u;
    asm("cvt.rna.tf32.f32 %0, %1;" : "=r"(u) : "f"(v));
    return __uint_as_float(u);
}
__device__ __forceinline__ void mma_tf32(float* c,
    uint32_t a0, uint32_t a1, uint32_t a2, uint32_t a3,
    uint32_t b0, uint32_t b1)
{
    asm volatile(
        "mma.sync.aligned.m16n8k8.row.col.f32.tf32.tf32.f32 "
        "{%0,%1,%2,%3}, {%4,%5,%6,%7}, {%8,%9}, {%0,%1,%2,%3};"
        : "+f"(c[0]), "+f"(c[1]), "+f"(c[2]), "+f"(c[3])
        : "r"(a0), "r"(a1), "r"(a2), "r"(a3), "r"(b0), "r"(b1));
}

// ================= scratch =================
__device__ float g_xcat[(size_t)Mv*1024];
__device__ float g_v1[(size_t)Mv*512];
__device__ float g_mag[(size_t)Mv*512];
__device__ float g_qd[(size_t)Mv*512];
__device__ float g_cqp[(size_t)Mv*128], g_sqp[(size_t)Mv*128];
__device__ float g_csp[(size_t)Mv*128], g_ssp[(size_t)Mv*128];
__device__ float g_gv[(size_t)Mv*8], g_gate[Mv];
__device__ float g_s1g[(size_t)Mv*512];
__device__ float g_posret[(size_t)Mv*512];
__device__ float g_ccat[(size_t)Mv*1024];
__device__ float g_ln[(size_t)Mv*1024];
__device__ float g_h1[(size_t)Mv*1024];
__device__ float g_wt[3276800];
__device__ float g_bcat[1664];
__device__ float g_pctx[Bv*NCv*Dv];
__device__ float g_pmc[Bv*NCv*Dv], g_pms[Bv*NCv*Dv], g_pmm[Bv*NCv*Dv];
__device__ float g_pkc[Bv*NCv*Pv*Vv], g_pks[Bv*NCv*Pv*Vv], g_pg[Bv*NCv];

// arena offsets (floats)
#define WT_PROJ 0
#define WT_O    851968
#define WT_S1   1114112
#define WT_S2   1638400
#define WT_T1   1703936
#define WT_T2   2752512

// ================= batched transpose+tf32-round =================
struct TTable {
    const float* src[9];
    float* dst[9];
    int K[9], N[9], t0[9];
};
__global__ void __launch_bounds__(256) transpose_all(TTable tt) {
    __shared__ float t[32][33];
    int bid = blockIdx.x;
    int w = 8;
#pragma unroll
    for (int i = 8; i >= 0; i--) if (bid >= tt.t0[i]) { w = i; break; }
    int tl = bid - tt.t0[w];
    int K = tt.K[w], N = tt.N[w];
    int tilesK = K >> 5;
    int k0 = (tl % tilesK) * 32, n0 = (tl / tilesK) * 32;
    const float* W = tt.src[w];
    float* WT = tt.dst[w];
    int tx = threadIdx.x & 31, ty = threadIdx.x >> 5;
#pragma unroll
    for (int i = ty; i < 32; i += 8) t[i][tx] = W[(size_t)(k0 + i) * N + n0 + tx];
    __syncthreads();
#pragma unroll
    for (int i = ty; i < 32; i += 8)
        WT[(size_t)(n0 + i) * K + k0 + tx] = f2tf32f(t[tx][i]);
}

// ================= bias concat =================
__global__ void bias_concat(const float* b_v, const float* b_m,
                            const float* b_q, const float* b_ke) {
    int i = blockIdx.x * blockDim.x + threadIdx.x;
    if (i < 512)        g_bcat[i] = b_v[i];
    else if (i < 1024)  g_bcat[i] = b_m[i - 512];
    else if (i < 1536)  g_bcat[i] = b_q[i - 1024];
    else if (i < 1664)  g_bcat[i] = b_ke[i - 1536];
}

// ================= tf32 mma.sync GEMM, 128x128 tile, 2-stage, 3 CTAs/SM =================
// epi: 0 none, 1 sigmoid*|*eptr|, 2 exact gelu, 4 +eptr residual,
//      5 sincos(tanh*PI)->C,C2, 6 merged-proj (v1|mag|qd|ke-sincos)
#define LDA 36
#define STAGE_F (256 * LDA)
__global__ void __launch_bounds__(256, 3) mma_gemm(
    const float* __restrict__ A, const float* __restrict__ WT,
    const float* __restrict__ bias,
    float* __restrict__ C, float* __restrict__ C2, float* __restrict__ C3,
    float* __restrict__ C4, float* __restrict__ C5,
    int K, int ldc, int epi, const float* __restrict__ eptr)
{
    extern __shared__ float sm[];
    const int tid = threadIdx.x, wid = tid >> 5, lane = tid & 31;
    const int warp_m = wid & 3, warp_n = wid >> 2;   // 4 x 2
    const int n0 = blockIdx.x * 128, m0 = blockIdx.y * 128;
    const int NK = K >> 5;
    const int lq = lane >> 2, lr = lane & 3;

    float c[2][8][4];
#pragma unroll
    for (int mi = 0; mi < 2; mi++)
#pragma unroll
        for (int j = 0; j < 8; j++)
#pragma unroll
            for (int q = 0; q < 4; q++) c[mi][j][q] = 0.f;

    auto load_tile = [&](int kt, int buf) {
        float* dst = sm + buf * STAGE_F;
#pragma unroll
        for (int i = 0; i < 4; i++) {
            int idx = tid + i * 256;
            int row = idx >> 3, cq = idx & 7;
            cp16(smem_u32(dst + row * LDA + cq * 4),
                 A + (size_t)(m0 + row) * K + kt * 32 + cq * 4);
        }
#pragma unroll
        for (int i = 0; i < 4; i++) {
            int idx = tid + i * 256;
            int row = idx >> 3, cq = idx & 7;
            cp16(smem_u32(dst + 128 * LDA + row * LDA + cq * 4),
                 WT + (size_t)(n0 + row) * K + kt * 32 + cq * 4);
        }
        CP_COMMIT();
    };

    load_tile(0, 0);

    for (int kt = 0; kt < NK; kt++) {
        int buf = kt & 1;
        if (kt + 1 < NK) load_tile(kt + 1, buf ^ 1);
        if (kt + 1 < NK) { CP_WAIT1(); } else { CP_WAIT0(); }
        __syncthreads();

        const uint32_t* As = (const uint32_t*)(sm + buf * STAGE_F);
        const uint32_t* Bs = As + 128 * LDA;
#pragma unroll
        for (int ks = 0; ks < 4; ks++) {
            int kb = ks * 8;
            uint32_t a[2][4];
#pragma unroll
            for (int mi = 0; mi < 2; mi++) {
                int mr = warp_m * 32 + mi * 16 + lq;
                a[mi][0] = As[mr * LDA + kb + lr];
                a[mi][1] = As[(mr + 8) * LDA + kb + lr];
                a[mi][2] = As[mr * LDA + kb + 4 + lr];
                a[mi][3] = As[(mr + 8) * LDA + kb + 4 + lr];
            }
#pragma unroll
            for (int j = 0; j < 8; j++) {
                int nr = warp_n * 64 + j * 8 + lq;
                uint32_t b0 = Bs[nr * LDA + kb + lr];
                uint32_t b1 = Bs[nr * LDA + kb + 4 + lr];
                mma_tf32(c[0][j], a[0][0], a[0][1], a[0][2], a[0][3], b0, b1);
                mma_tf32(c[1][j], a[1][0], a[1][1], a[1][2], a[1][3], b0, b1);
            }
        }
        __syncthreads();
    }

    // ---------------- epilogue ----------------
    float scale1 = (epi == 1 || epi == 6) ? fabsf(*eptr) : 0.f;
    int seg = n0 >> 9;
#pragma unroll
    for (int mi = 0; mi < 2; mi++) {
#pragma unroll
        for (int j = 0; j < 8; j++) {
            int gm = m0 + warp_m * 32 + mi * 16 + lq;
            int gn = n0 + warp_n * 64 + j * 8 + lr * 2;
            float b0 = bias[gn], b1 = bias[gn + 1];
#pragma unroll
            for (int h = 0; h < 2; h++) {
                int gmr = gm + h * 8;
                float v0 = c[mi][j][h * 2 + 0] + b0;
                float v1 = c[mi][j][h * 2 + 1] + b1;
                if (epi == 6) {
                    if (seg == 0) {
                        C[(size_t)gmr * 512 + gn] = v0;
                        C[(size_t)gmr * 512 + gn + 1] = v1;
                    } else if (seg == 1) {
                        size_t oo = (size_t)gmr * 512 + gn - 512;
                        C2[oo]     = scale1 / (1.f + expf(-v0));
                        C2[oo + 1] = scale1 / (1.f + expf(-v1));
                    } else if (seg == 2) {
                        size_t oo = (size_t)gmr * 512 + gn - 1024;
                        C3[oo] = v0; C3[oo + 1] = v1;
                    } else {
                        size_t oo = (size_t)gmr * 128 + gn - 1536;
                        float t0 = tanhf(v0) * PI_F, t1 = tanhf(v1) * PI_F;
                        float s0, cc0, s1, cc1;
                        sincosf(t0, &s0, &cc0);
                        sincosf(t1, &s1, &cc1);
                        C4[oo] = cc0; C4[oo + 1] = cc1;
                        C5[oo] = s0;  C5[oo + 1] = s1;
                    }
                    continue;
                }
                size_t oo = (size_t)gmr * ldc + gn;
                if (epi == 1) {
                    v0 = scale1 / (1.f + expf(-v0));
                    v1 = scale1 / (1.f + expf(-v1));
                } else if (epi == 2) {
                    v0 = 0.5f * v0 * (1.f + erff(v0 * 0.70710678118654752f));
                    v1 = 0.5f * v1 * (1.f + erff(v1 * 0.70710678118654752f));
                } else if (epi == 4) {
                    v0 += eptr[oo];
                    v1 += eptr[oo + 1];
                } else if (epi == 5) {
                    float t0 = tanhf(v0) * PI_F, t1 = tanhf(v1) * PI_F;
                    float s0, c0, s1, c1;
                    sincosf(t0, &s0, &c0);
                    sincosf(t1, &s1, &c1);
                    C[oo] = c0; C[oo + 1] = c1;
                    C2[oo] = s0; C2[oo + 1] = s1;
                    continue;
                }
                C[oo] = v0; C[oo + 1] = v1;
            }
        }
    }
}

// ================= context_avg scan =================
__global__ void ctx_p1(const float* __restrict__ x) {
    int bc = blockIdx.x; int b = bc >> NC_SH, c = bc & NC_MASK;
    int d = blockIdx.y * 128 + threadIdx.x;
    const float* xp = x + ((size_t)(b * Lv + c * LCv)) * Dv + d;
    float s0 = 0.f, s1 = 0.f, s2 = 0.f, s3 = 0.f;
#pragma unroll 4
    for (int i = 0; i < LCv; i += 4) {
        s0 += xp[(size_t)i * Dv];
        s1 += xp[(size_t)(i + 1) * Dv];
        s2 += xp[(size_t)(i + 2) * Dv];
        s3 += xp[(size_t)(i + 3) * Dv];
    }
    g_pctx[(size_t)bc * Dv + d] = (s0 + s1) + (s2 + s3);
}
// batched-load register-scan (MLP=NCv)
__global__ void ctx_p2() {
    int idx = blockIdx.x * blockDim.x + threadIdx.x;
    if (idx >= Bv * Dv) return;
    int b = idx / Dv, d = idx % Dv;
    float v[NCv];
#pragma unroll
    for (int c = 0; c < NCv; c++)
        v[c] = g_pctx[((size_t)(b * NCv + c)) * Dv + d];
    float run = 0.f;
#pragma unroll
    for (int c = 0; c < NCv; c++) { float t = v[c]; v[c] = run; run += t; }
#pragma unroll
    for (int c = 0; c < NCv; c++)
        g_pctx[((size_t)(b * NCv + c)) * Dv + d] = v[c];
}
__global__ void ctx_p3(const float* __restrict__ x) {
    int bc = blockIdx.x; int b = bc >> NC_SH, c = bc & NC_MASK;
    int d = blockIdx.y * 128 + threadIdx.x;
    const float* xp = x + ((size_t)(b * Lv + c * LCv)) * Dv + d;
    float s = g_pctx[(size_t)bc * Dv + d];
    for (int i = 0; i < LCv; i++) {
        int l = c * LCv + i;
        float xv = xp[(size_t)i * Dv];
        s += xv;
        size_t row = (size_t)(b * Lv + l);
        g_xcat[row * 1024 + d] = xv;
        g_xcat[row * 1024 + 512 + d] = s / (float)(l + 1);
    }
}

// ================= values*gate =================
__global__ void __launch_bounds__(256) vg_kernel(
    const float* __restrict__ x, const float* __restrict__ w_ve,
    const float* __restrict__ b_ve, const float* __restrict__ w_g,
    const float* __restrict__ b_g)
{
    __shared__ float sw[8 * 512];
    __shared__ float sg[512];
    int tid = threadIdx.x;
    for (int idx = tid; idx < 512 * 8; idx += 256) {
        int k = idx >> 3, v = idx & 7;
        sw[v * 512 + k] = w_ve[idx];
    }
    for (int idx = tid; idx < 512; idx += 256) sg[idx] = w_g[idx];
    __syncthreads();
    int lane = tid & 31, w = tid >> 5;
    int m = blockIdx.x * 8 + w;
    const float* xr = x + (size_t)m * 512;
    float acc[8] = {0, 0, 0, 0, 0, 0, 0, 0}, ag = 0.f;
    for (int j = 0; j < 16; j++) {
        int k = lane + 32 * j;
        float xk = xr[k];
#pragma unroll
        for (int v = 0; v < 8; v++) acc[v] += xk * sw[v * 512 + k];
        ag += xk * sg[k];
    }
#pragma unroll
    for (int o = 16; o; o >>= 1) {
#pragma unroll
        for (int v = 0; v < 8; v++) acc[v] += __shfl_xor_sync(0xffffffffu, acc[v], o);
        ag += __shfl_xor_sync(0xffffffffu, ag, o);
    }
    if (lane == 0) {
        float gate = 1.f / (1.f + expf(-(ag + b_g[0])));
        g_gate[m] = gate;
#pragma unroll
        for (int v = 0; v < 8; v++) g_gv[(size_t)m * 8 + v] = (acc[v] + b_ve[v]) * gate;
    }
}

// ================= mem1 scan + fused pos_ret (phi sincos inline) =================
__global__ void mem1_p1(const float* __restrict__ pos) {
    int bc = blockIdx.x; int b = bc >> NC_SH, c = bc & NC_MASK;
    int d = blockIdx.y * 128 + threadIdx.x;
    size_t base = ((size_t)(b * Lv + c * LCv)) * Dv + d;
    float sc = 0.f, ss = 0.f, sm = 0.f;
    for (int i = 0; i < LCv; i++) {
        int lg = c * LCv + i;
        float mag = g_mag[base + (size_t)i * Dv];
        float v1  = g_v1[base + (size_t)i * Dv];
        float w = mag * v1;
        float sphi, cphi;
        sincosf(pos[(size_t)lg * Dv + d], &sphi, &cphi);
        sc += w * cphi;
        ss += w * sphi;
        sm += mag;
    }
    size_t o = (size_t)bc * Dv + d;
    g_pmc[o] = sc; g_pms[o] = ss; g_pmm[o] = sm;
}
// batched-load register-scan over 3 arrays (selector on blockIdx.y)
__global__ void mem1_p2() {
    int idx = blockIdx.x * blockDim.x + threadIdx.x;
    if (idx >= Bv * Dv) return;
    int sel = blockIdx.y;
    float* arr = (sel == 0) ? g_pmc : ((sel == 1) ? g_pms : g_pmm);
    int b = idx / Dv, d = idx % Dv;
    float v[NCv];
#pragma unroll
    for (int c = 0; c < NCv; c++)
        v[c] = arr[((size_t)(b * NCv + c)) * Dv + d];
    float run = 0.f;
#pragma unroll
    for (int c = 0; c < NCv; c++) { float t = v[c]; v[c] = run; run += t; }
#pragma unroll
    for (int c = 0; c < NCv; c++)
        arr[((size_t)(b * NCv + c)) * Dv + d] = v[c];
}
__global__ void mem1_p3(const float* __restrict__ pos) {
    int bc = blockIdx.x; int b = bc >> NC_SH, c = bc & NC_MASK;
    int d = blockIdx.y * 128 + threadIdx.x;
    size_t base = ((size_t)(b * Lv + c * LCv)) * Dv + d;
    size_t po = (size_t)bc * Dv + d;
    float sc = g_pmc[po], ss = g_pms[po], sm = g_pmm[po];
    for (int i = 0; i < LCv; i++) {
        int lg = c * LCv + i;
        float mag = g_mag[base + (size_t)i * Dv];
        float v1  = g_v1[base + (size_t)i * Dv];
        float w = mag * v1;
        float pp = pos[(size_t)lg * Dv + d];
        float sphi, cphi;
        sincosf(pp, &sphi, &cphi);
        sc += w * cphi;
        ss += w * sphi;
        sm += mag;
        float ph = pp + g_qd[base + (size_t)i * Dv];
        float sq, cq;
        sincosf(ph, &sq, &cq);
        g_posret[base + (size_t)i * Dv] =
            (sc * cq + ss * sq) * rsqrtf(sm + 1e-8f) * INV_SQRT_D;
    }
}

// ================= kv phasor scan + retrieval =================
__global__ void __launch_bounds__(256) kv_p1() {
    __shared__ float s_csp[128], s_ssp[128], s_gv[8];
    int bc = blockIdx.x; int b = bc >> NC_SH, c = bc & NC_MASK;
    int tid = threadIdx.x;
    int v = tid & 7, p_base = (tid >> 3) * 4;
    float aC[4] = {0, 0, 0, 0}, aS[4] = {0, 0, 0, 0};
    float gs = 0.f;
    for (int i = 0; i < LCv; i++) {
        int m = b * Lv + c * LCv + i;
        if (tid < 128) s_csp[tid] = g_csp[(size_t)m * 128 + tid];
        else           s_ssp[tid - 128] = g_ssp[(size_t)m * 128 + (tid - 128)];
        if (tid < 8) s_gv[tid] = g_gv[(size_t)m * 8 + tid];
        if (tid == 0) gs += g_gate[m];
        __syncthreads();
        float gvv = s_gv[v];
#pragma unroll
        for (int j = 0; j < 4; j++) {
            aC[j] += s_csp[p_base + j] * gvv;
            aS[j] += s_ssp[p_base + j] * gvv;
        }
        __syncthreads();
    }
#pragma unroll
    for (int j = 0; j < 4; j++) {
        size_t o = (size_t)bc * 1024 + (size_t)(p_base + j) * 8 + v;
        g_pkc[o] = aC[j]; g_pks[o] = aS[j];
    }
    if (tid == 0) g_pg[bc] = gs;
}
// batched-load register-scan; sel via blockIdx.y; gate handled by block 0
__global__ void kv_p2() {
    int idx = blockIdx.x * blockDim.x + threadIdx.x;
    if (idx < Bv * Pv * Vv) {
        float* arr = blockIdx.y ? g_pks : g_pkc;
        int b = idx >> 10, pv = idx & 1023;
        float v[NCv];
#pragma unroll
        for (int c = 0; c < NCv; c++)
            v[c] = arr[((size_t)(b * NCv + c)) * 1024 + pv];
        float run = 0.f;
#pragma unroll
        for (int c = 0; c < NCv; c++) { float t = v[c]; v[c] = run; run += t; }
#pragma unroll
        for (int c = 0; c < NCv; c++)
            arr[((size_t)(b * NCv + c)) * 1024 + pv] = v[c];
    }
    if (blockIdx.x == 0 && blockIdx.y == 0 && idx < Bv) {
        float v[NCv];
#pragma unroll
        for (int c = 0; c < NCv; c++) v[c] = g_pg[(size_t)idx * NCv + c];
        float run = 0.f;
#pragma unroll
        for (int c = 0; c < NCv; c++) { float t = v[c]; v[c] = run; run += t; }
#pragma unroll
        for (int c = 0; c < NCv; c++) g_pg[(size_t)idx * NCv + c] = v[c];
    }
}
// fused: scan + retrieval + kv_out (writes ccat[:,512:1024])
__global__ void __launch_bounds__(256) kv_p3(
    const float* __restrict__ w_kv, const float* __restrict__ b_kv)
{
    __shared__ float s_csp[128], s_ssp[128], s_cqp[128], s_sqp[128], s_gv[8];
    __shared__ float s_r[64];
    __shared__ float s_kvr[8];
    __shared__ float s_wkv[8 * 512];
    __shared__ float s_bkv[512];
    int bc = blockIdx.x; int b = bc >> NC_SH, c = bc & NC_MASK;
    int tid = threadIdx.x;
    int v = tid & 7, p_base = (tid >> 3) * 4;
    for (int i = tid; i < 8 * 512; i += 256) s_wkv[i] = w_kv[i];
    for (int i = tid; i < 512; i += 256) s_bkv[i] = b_kv[i];
    float aC[4], aS[4];
#pragma unroll
    for (int j = 0; j < 4; j++) {
        size_t o = (size_t)bc * 1024 + (size_t)(p_base + j) * 8 + v;
        aC[j] = g_pkc[o]; aS[j] = g_pks[o];
    }
    float gsum = (tid == 0) ? g_pg[bc] : 0.f;
    __syncthreads();
    for (int i = 0; i < LCv; i++) {
        int m = b * Lv + c * LCv + i;
        if (tid < 128) {
            s_csp[tid] = g_csp[(size_t)m * 128 + tid];
            s_cqp[tid] = g_cqp[(size_t)m * 128 + tid];
        } else {
            int t = tid - 128;
            s_ssp[t] = g_ssp[(size_t)m * 128 + t];
            s_sqp[t] = g_sqp[(size_t)m * 128 + t];
        }
        if (tid < 8) s_gv[tid] = g_gv[(size_t)m * 8 + tid];
        __syncthreads();
        float gvv = s_gv[v];
        float pr = 0.f;
#pragma unroll
        for (int j = 0; j < 4; j++) {
            int p = p_base + j;
            aC[j] += s_csp[p] * gvv;
            aS[j] += s_ssp[p] * gvv;
            pr += s_cqp[p] * aC[j] + s_sqp[p] * aS[j];
        }
        pr += __shfl_xor_sync(0xffffffffu, pr, 8);
        pr += __shfl_xor_sync(0xffffffffu, pr, 16);
        if ((tid & 31) < 8) s_r[(tid >> 5) * 8 + (tid & 7)] = pr;
        if (tid == 0) gsum += g_gate[m];
        __syncthreads();
        if (tid < 8) {
            float accv = 0.f;
#pragma unroll
            for (int w = 0; w < 8; w++) accv += s_r[w * 8 + tid];
            float inv = rsqrtf(fmaxf(__shfl_sync(0x000000ffu, gsum, 0, 8), 1.0f));
            s_kvr[tid] = accv * inv * INV_SQRT_P;
        }
        __syncthreads();
        float k0 = s_kvr[0], k1 = s_kvr[1], k2 = s_kvr[2], k3 = s_kvr[3];
        float k4 = s_kvr[4], k5 = s_kvr[5], k6 = s_kvr[6], k7 = s_kvr[7];
#pragma unroll
        for (int h = 0; h < 2; h++) {
            int n = tid + h * 256;
            float o = s_bkv[n];
            o += k0 * s_wkv[n];
            o += k1 * s_wkv[512 + n];
            o += k2 * s_wkv[1024 + n];
            o += k3 * s_wkv[1536 + n];
            o += k4 * s_wkv[2048 + n];
            o += k5 * s_wkv[2560 + n];
            o += k6 * s_wkv[3072 + n];
            o += k7 * s_wkv[3584 + n];
            g_ccat[(size_t)m * 1024 + 512 + n] = o;
        }
        __syncthreads();
    }
}

// ================= LayerNorm =================
__global__ void __launch_bounds__(256) ln_kernel(
    const float* __restrict__ lng, const float* __restrict__ lnb)
{
    int m = blockIdx.x, tid = threadIdx.x;
    const float4* row = (const float4*)(g_ccat + (size_t)m * 1024);
    float4 val = row[tid];
    float s = val.x + val.y + val.z + val.w;
    float q = val.x * val.x + val.y * val.y + val.z * val.z + val.w * val.w;
#pragma unroll
    for (int o = 16; o; o >>= 1) {
        s += __shfl_xor_sync(0xffffffffu, s, o);
        q += __shfl_xor_sync(0xffffffffu, q, o);
    }
    __shared__ float ss[8], sq[8];
    __shared__ float smu, srs;
    if ((tid & 31) == 0) { ss[tid >> 5] = s; sq[tid >> 5] = q; }
    __syncthreads();
    if (tid == 0) {
        float S = 0.f, Q = 0.f;
#pragma unroll
        for (int w = 0; w < 8; w++) { S += ss[w]; Q += sq[w]; }
        float mu = S * (1.f / 1024.f);
        float var = Q * (1.f / 1024.f) - mu * mu;
        smu = mu; srs = rsqrtf(var + 1e-5f);
    }
    __syncthreads();
    float mu = smu, rs = srs;
    float4 g4 = ((const float4*)lng)[tid];
    float4 b4 = ((const float4*)lnb)[tid];
    float4 o;
    o.x = (val.x - mu) * rs * g4.x + b4.x;
    o.y = (val.y - mu) * rs * g4.y + b4.y;
    o.z = (val.z - mu) * rs * g4.z + b4.z;
    o.w = (val.w - mu) * rs * g4.w + b4.w;
    ((float4*)(g_ln + (size_t)m * 1024))[tid] = o;
}

// ================= launch =================
extern "C" void kernel_launch(void* const* d_in, const int* in_sizes, int n_in,
                              void* d_out, int out_size)
{
    const float* x    = (const float*)d_in[0];
    const float* pos  = (const float*)d_in[1];
    const float* ms   = (const float*)d_in[2];
    const float* w_v  = (const float*)d_in[3];
    const float* b_v  = (const float*)d_in[4];
    const float* w_o  = (const float*)d_in[5];
    const float* b_o  = (const float*)d_in[6];
    const float* w_m  = (const float*)d_in[7];
    const float* b_m  = (const float*)d_in[8];
    const float* w_q  = (const float*)d_in[9];
    const float* b_q  = (const float*)d_in[10];
    const float* w_ke = (const float*)d_in[11];
    const float* b_ke = (const float*)d_in[12];
    const float* w_ve = (const float*)d_in[13];
    const float* b_ve = (const float*)d_in[14];
    const float* w_s1 = (const float*)d_in[15];
    const float* b_s1 = (const float*)d_in[16];
    const float* w_s2 = (const float*)d_in[17];
    const float* b_s2 = (const float*)d_in[18];
    const float* w_g  = (const float*)d_in[19];
    const float* b_g  = (const float*)d_in[20];
    const float* w_kv = (const float*)d_in[21];
    const float* b_kv = (const float*)d_in[22];
    const float* lng  = (const float*)d_in[23];
    const float* lnb  = (const float*)d_in[24];
    const float* w_t1 = (const float*)d_in[25];
    const float* b_t1 = (const float*)d_in[26];
    const float* w_t2 = (const float*)d_in[27];
    const float* b_t2 = (const float*)d_in[28];
    float* out = (float*)d_out;

    float *p_xcat, *p_v1, *p_mag, *p_qd, *p_s1g, *p_posret, *p_ccat, *p_ln,
          *p_h1, *p_wt, *p_cqp, *p_sqp, *p_csp, *p_ssp, *p_bcat;
    cudaGetSymbolAddress((void**)&p_xcat, g_xcat);
    cudaGetSymbolAddress((void**)&p_v1, g_v1);
    cudaGetSymbolAddress((void**)&p_mag, g_mag);
    cudaGetSymbolAddress((void**)&p_qd, g_qd);
    cudaGetSymbolAddress((void**)&p_s1g, g_s1g);
    cudaGetSymbolAddress((void**)&p_posret, g_posret);
    cudaGetSymbolAddress((void**)&p_ccat, g_ccat);
    cudaGetSymbolAddress((void**)&p_ln, g_ln);
    cudaGetSymbolAddress((void**)&p_h1, g_h1);
    cudaGetSymbolAddress((void**)&p_wt, g_wt);
    cudaGetSymbolAddress((void**)&p_cqp, g_cqp);
    cudaGetSymbolAddress((void**)&p_sqp, g_sqp);
    cudaGetSymbolAddress((void**)&p_csp, g_csp);
    cudaGetSymbolAddress((void**)&p_ssp, g_ssp);
    cudaGetSymbolAddress((void**)&p_bcat, g_bcat);

    float* wt_proj = p_wt + WT_PROJ;
    float* wt_o    = p_wt + WT_O;
    float* wt_s1   = p_wt + WT_S1;
    float* wt_s2   = p_wt + WT_S2;
    float* wt_t1   = p_wt + WT_T1;
    float* wt_t2   = p_wt + WT_T2;

    const int SMEM = 2 * STAGE_F * 4;  // 73728 B -> 3 CTAs/SM
    cudaFuncSetAttribute(mma_gemm, cudaFuncAttributeMaxDynamicSharedMemorySize, SMEM);

    TTable tt;
    tt.src[0] = w_v;  tt.dst[0] = wt_proj;              tt.K[0] = 512;  tt.N[0] = 512;
    tt.src[1] = w_m;  tt.dst[1] = wt_proj + 512 * 512;  tt.K[1] = 512;  tt.N[1] = 512;
    tt.src[2] = w_q;  tt.dst[2] = wt_proj + 1024 * 512; tt.K[2] = 512;  tt.N[2] = 512;
    tt.src[3] = w_ke; tt.dst[3] = wt_proj + 1536 * 512; tt.K[3] = 512;  tt.N[3] = 128;
    tt.src[4] = w_o;  tt.dst[4] = wt_o;                 tt.K[4] = 512;  tt.N[4] = 512;
    tt.src[5] = w_s1; tt.dst[5] = wt_s1;                tt.K[5] = 1024; tt.N[5] = 512;
    tt.src[6] = w_s2; tt.dst[6] = wt_s2;                tt.K[6] = 512;  tt.N[6] = 128;
    tt.src[7] = w_t1; tt.dst[7] = wt_t1;                tt.K[7] = 1024; tt.N[7] = 1024;
    tt.src[8] = w_t2; tt.dst[8] = wt_t2;                tt.K[8] = 1024; tt.N[8] = 512;
    int acc = 0;
    for (int i = 0; i < 9; i++) {
        tt.t0[i] = acc;
        acc += (tt.K[i] >> 5) * (tt.N[i] >> 5);
    }
    transpose_all<<<acc, 256>>>(tt);
    bias_concat<<<7, 256>>>(b_v, b_m, b_q, b_ke);

    dim3 tb(256);
    dim3 gScan(Bv * NCv, Dv / 128);

    ctx_p1<<<gScan, 128>>>(x);
    ctx_p2<<<(Bv * Dv + 255) / 256, 256>>>();
    ctx_p3<<<gScan, 128>>>(x);

    // merged projections: v | mag | qd | ke-sincos
    mma_gemm<<<dim3(13, 128), tb, SMEM>>>(x, wt_proj, p_bcat,
        p_v1, p_mag, p_qd, p_cqp, p_sqp, 512, 512, 6, ms);
    vg_kernel<<<Mv / 8, 256>>>(x, w_ve, b_ve, w_g, b_g);
    mma_gemm<<<dim3(4, 128), tb, SMEM>>>(p_xcat, wt_s1, b_s1,
        p_s1g, nullptr, nullptr, nullptr, nullptr, 1024, 512, 2, nullptr);
    mma_gemm<<<dim3(1, 128), tb, SMEM>>>(p_s1g, wt_s2, b_s2,
        p_csp, p_ssp, nullptr, nullptr, nullptr, 512, 128, 5, nullptr);

    // mem1 scan + pos_out
    mem1_p1<<<gScan, 128>>>(pos);
    mem1_p2<<<dim3((Bv * Dv + 255) / 256, 3), 256>>>();
    mem1_p3<<<gScan, 128>>>(pos);
    mma_gemm<<<dim3(4, 128), tb, SMEM>>>(p_posret, wt_o, b_o,
        p_ccat, nullptr, nullptr, nullptr, nullptr, 512, 1024, 0, nullptr);

    // kv scan + retrieval + fused kv_out
    kv_p1<<<Bv * NCv, 256>>>();
    kv_p2<<<dim3((Bv * Pv * Vv + 255) / 256, 2), 256>>>();
    kv_p3<<<Bv * NCv, 256>>>(w_kv, b_kv);

    // LN + output MLP + residual
    ln_kernel<<<Mv, 256>>>(lng, lnb);
    mma_gemm<<<dim3(8, 128), tb, SMEM>>>(p_ln, wt_t1, b_t1,
        p_h1, nullptr, nullptr, nullptr, nullptr, 1024, 1024, 2, nullptr);
    mma_gemm<<<dim3(4, 128), tb, SMEM>>>(p_h1, wt_t2, b_t2,
        out, nullptr, nullptr, nullptr, nullptr, 1024, 512, 4, x);
}

// round 9
// speedup vs baseline: 1.1484x; 1.1484x over previous
#include <cuda_runtime.h>
#include <math.h>
#include <stdint.h>

#define Bv 4
#define Lv 4096
#define Dv 512
#define Pv 128
#define Vv 8
#define Mv (Bv*Lv)          // 16384
#define NCv 64
#define NC_SH 6
#define NC_MASK 63
#define LCv (Lv/NCv)        // 64
#define PI_F 3.14159265358979323846f
#define INV_SQRT_D 0.044194173824159216f
#define INV_SQRT_P 0.08838834764831845f

// ================= helpers =================
__device__ __forceinline__ uint32_t smem_u32(const void* p) {
    uint32_t a;
    asm("{ .reg .u64 t; cvta.to.shared.u64 t, %1; cvt.u32.u64 %0, t; }" : "=r"(a) : "l"(p));
    return a;
}
__device__ __forceinline__ void cp16(uint32_t s, const void* g) {
    asm volatile("cp.async.cg.shared.global [%0], [%1], 16;" :: "r"(s), "l"(g) : "memory");
}
#define CP_COMMIT() asm volatile("cp.async.commit_group;" ::: "memory")
#define CP_WAIT1()  asm volatile("cp.async.wait_group 1;" ::: "memory")
#define CP_WAIT0()  asm volatile("cp.async.wait_group 0;" ::: "memory")

__device__ __forceinline__ float f2tf32f(float v) {
    uint32_t u;
    asm("cvt.rna.tf32.f32 %0, %1;" : "=r"(u) : "f"(v));
    return __uint_as_float(u);
}
__device__ __forceinline__ void mma_tf32(float* c,
    uint32_t a0, uint32_t a1, uint32_t a2, uint32_t a3,
    uint32_t b0, uint32_t b1)
{
    asm volatile(
        "mma.sync.aligned.m16n8k8.row.col.f32.tf32.tf32.f32 "
        "{%0,%1,%2,%3}, {%4,%5,%6,%7}, {%8,%9}, {%0,%1,%2,%3};"
        : "+f"(c[0]), "+f"(c[1]), "+f"(c[2]), "+f"(c[3])
        : "r"(a0), "r"(a1), "r"(a2), "r"(a3), "r"(b0), "r"(b1));
}

// ================= scratch =================
__device__ float g_xcat[(size_t)Mv*1024];
__device__ float g_v1[(size_t)Mv*512];
__device__ float g_mag[(size_t)Mv*512];
__device__ float g_qd[(size_t)Mv*512];
__device__ float g_cqp[(size_t)Mv*128], g_sqp[(size_t)Mv*128];
__device__ float g_csp[(size_t)Mv*128], g_ssp[(size_t)Mv*128];
__device__ float g_gv[(size_t)Mv*8], g_gate[Mv];
__device__ float g_s1g[(size_t)Mv*512];
__device__ float g_posret[(size_t)Mv*512];
__device__ float g_ccat[(size_t)Mv*1024];
__device__ float g_ln[(size_t)Mv*1024];
__device__ float g_h1[(size_t)Mv*1024];
__device__ float g_wt[3276800];
__device__ float g_bcat[1664];
__device__ float g_pctx[Bv*NCv*Dv];
__device__ float g_pmc[Bv*NCv*Dv], g_pms[Bv*NCv*Dv], g_pmm[Bv*NCv*Dv];
__device__ float g_pkc[Bv*NCv*Pv*Vv], g_pks[Bv*NCv*Pv*Vv], g_pg[Bv*NCv];

// arena offsets (floats)
#define WT_PROJ 0
#define WT_O    851968
#define WT_S1   1114112
#define WT_S2   1638400
#define WT_T1   1703936
#define WT_T2   2752512

// ================= batched transpose+tf32-round =================
struct TTable {
    const float* src[9];
    float* dst[9];
    int K[9], N[9], t0[9];
};
__global__ void __launch_bounds__(256) transpose_all(TTable tt) {
    __shared__ float t[32][33];
    int bid = blockIdx.x;
    int w = 8;
#pragma unroll
    for (int i = 8; i >= 0; i--) if (bid >= tt.t0[i]) { w = i; break; }
    int tl = bid - tt.t0[w];
    int K = tt.K[w], N = tt.N[w];
    int tilesK = K >> 5;
    int k0 = (tl % tilesK) * 32, n0 = (tl / tilesK) * 32;
    const float* W = tt.src[w];
    float* WT = tt.dst[w];
    int tx = threadIdx.x & 31, ty = threadIdx.x >> 5;
#pragma unroll
    for (int i = ty; i < 32; i += 8) t[i][tx] = W[(size_t)(k0 + i) * N + n0 + tx];
    __syncthreads();
#pragma unroll
    for (int i = ty; i < 32; i += 8)
        WT[(size_t)(n0 + i) * K + k0 + tx] = f2tf32f(t[tx][i]);
}

// ================= bias concat =================
__global__ void bias_concat(const float* b_v, const float* b_m,
                            const float* b_q, const float* b_ke) {
    int i = blockIdx.x * blockDim.x + threadIdx.x;
    if (i < 512)        g_bcat[i] = b_v[i];
    else if (i < 1024)  g_bcat[i] = b_m[i - 512];
    else if (i < 1536)  g_bcat[i] = b_q[i - 1024];
    else if (i < 1664)  g_bcat[i] = b_ke[i - 1536];
}

// ================= tf32 mma.sync GEMM (R5 config: 128x128, 2-stage, 2 CTAs/SM) =================
// epi: 0 none, 1 sigmoid*|*eptr|, 2 exact gelu, 4 +eptr residual,
//      5 sincos(tanh*PI)->C,C2, 6 merged-proj (v1|mag|qd|ke-sincos)
#define LDA 36
#define STAGE_F (256 * LDA)
__global__ void __launch_bounds__(256, 2) mma_gemm(
    const float* __restrict__ A, const float* __restrict__ WT,
    const float* __restrict__ bias,
    float* __restrict__ C, float* __restrict__ C2, float* __restrict__ C3,
    float* __restrict__ C4, float* __restrict__ C5,
    int K, int ldc, int epi, const float* __restrict__ eptr)
{
    extern __shared__ float sm[];
    const int tid = threadIdx.x, wid = tid >> 5, lane = tid & 31;
    const int warp_m = wid & 3, warp_n = wid >> 2;   // 4 x 2
    const int n0 = blockIdx.x * 128, m0 = blockIdx.y * 128;
    const int NK = K >> 5;
    const int lq = lane >> 2, lr = lane & 3;

    float c[2][8][4];
#pragma unroll
    for (int mi = 0; mi < 2; mi++)
#pragma unroll
        for (int j = 0; j < 8; j++)
#pragma unroll
            for (int q = 0; q < 4; q++) c[mi][j][q] = 0.f;

    auto load_tile = [&](int kt, int buf) {
        float* dst = sm + buf * STAGE_F;
#pragma unroll
        for (int i = 0; i < 4; i++) {
            int idx = tid + i * 256;
            int row = idx >> 3, cq = idx & 7;
            cp16(smem_u32(dst + row * LDA + cq * 4),
                 A + (size_t)(m0 + row) * K + kt * 32 + cq * 4);
        }
#pragma unroll
        for (int i = 0; i < 4; i++) {
            int idx = tid + i * 256;
            int row = idx >> 3, cq = idx & 7;
            cp16(smem_u32(dst + 128 * LDA + row * LDA + cq * 4),
                 WT + (size_t)(n0 + row) * K + kt * 32 + cq * 4);
        }
        CP_COMMIT();
    };

    load_tile(0, 0);

    for (int kt = 0; kt < NK; kt++) {
        int buf = kt & 1;
        if (kt + 1 < NK) load_tile(kt + 1, buf ^ 1);
        if (kt + 1 < NK) { CP_WAIT1(); } else { CP_WAIT0(); }
        __syncthreads();

        const uint32_t* As = (const uint32_t*)(sm + buf * STAGE_F);
        const uint32_t* Bs = As + 128 * LDA;
#pragma unroll
        for (int ks = 0; ks < 4; ks++) {
            int kb = ks * 8;
            uint32_t a[2][4];
#pragma unroll
            for (int mi = 0; mi < 2; mi++) {
                int mr = warp_m * 32 + mi * 16 + lq;
                a[mi][0] = As[mr * LDA + kb + lr];
                a[mi][1] = As[(mr + 8) * LDA + kb + lr];
                a[mi][2] = As[mr * LDA + kb + 4 + lr];
                a[mi][3] = As[(mr + 8) * LDA + kb + 4 + lr];
            }
#pragma unroll
            for (int j = 0; j < 8; j++) {
                int nr = warp_n * 64 + j * 8 + lq;
                uint32_t b0 = Bs[nr * LDA + kb + lr];
                uint32_t b1 = Bs[nr * LDA + kb + 4 + lr];
                mma_tf32(c[0][j], a[0][0], a[0][1], a[0][2], a[0][3], b0, b1);
                mma_tf32(c[1][j], a[1][0], a[1][1], a[1][2], a[1][3], b0, b1);
            }
        }
        __syncthreads();
    }

    // ---------------- epilogue ----------------
    float scale1 = (epi == 1 || epi == 6) ? fabsf(*eptr) : 0.f;
    int seg = n0 >> 9;
#pragma unroll
    for (int mi = 0; mi < 2; mi++) {
#pragma unroll
        for (int j = 0; j < 8; j++) {
            int gm = m0 + warp_m * 32 + mi * 16 + lq;
            int gn = n0 + warp_n * 64 + j * 8 + lr * 2;
            float b0 = bias[gn], b1 = bias[gn + 1];
#pragma unroll
            for (int h = 0; h < 2; h++) {
                int gmr = gm + h * 8;
                float v0 = c[mi][j][h * 2 + 0] + b0;
                float v1 = c[mi][j][h * 2 + 1] + b1;
                if (epi == 6) {
                    if (seg == 0) {
                        C[(size_t)gmr * 512 + gn] = v0;
                        C[(size_t)gmr * 512 + gn + 1] = v1;
                    } else if (seg == 1) {
                        size_t oo = (size_t)gmr * 512 + gn - 512;
                        C2[oo]     = scale1 / (1.f + expf(-v0));
                        C2[oo + 1] = scale1 / (1.f + expf(-v1));
                    } else if (seg == 2) {
                        size_t oo = (size_t)gmr * 512 + gn - 1024;
                        C3[oo] = v0; C3[oo + 1] = v1;
                    } else {
                        size_t oo = (size_t)gmr * 128 + gn - 1536;
                        float t0 = tanhf(v0) * PI_F, t1 = tanhf(v1) * PI_F;
                        float s0, cc0, s1, cc1;
                        sincosf(t0, &s0, &cc0);
                        sincosf(t1, &s1, &cc1);
                        C4[oo] = cc0; C4[oo + 1] = cc1;
                        C5[oo] = s0;  C5[oo + 1] = s1;
                    }
                    continue;
                }
                size_t oo = (size_t)gmr * ldc + gn;
                if (epi == 1) {
                    v0 = scale1 / (1.f + expf(-v0));
                    v1 = scale1 / (1.f + expf(-v1));
                } else if (epi == 2) {
                    v0 = 0.5f * v0 * (1.f + erff(v0 * 0.70710678118654752f));
                    v1 = 0.5f * v1 * (1.f + erff(v1 * 0.70710678118654752f));
                } else if (epi == 4) {
                    v0 += eptr[oo];
                    v1 += eptr[oo + 1];
                } else if (epi == 5) {
                    float t0 = tanhf(v0) * PI_F, t1 = tanhf(v1) * PI_F;
                    float s0, c0, s1, c1;
                    sincosf(t0, &s0, &c0);
                    sincosf(t1, &s1, &c1);
                    C[oo] = c0; C[oo + 1] = c1;
                    C2[oo] = s0; C2[oo + 1] = s1;
                    continue;
                }
                C[oo] = v0; C[oo + 1] = v1;
            }
        }
    }
}

// ================= context_avg scan =================
__global__ void ctx_p1(const float* __restrict__ x) {
    int bc = blockIdx.x; int b = bc >> NC_SH, c = bc & NC_MASK;
    int d = blockIdx.y * 128 + threadIdx.x;
    const float* xp = x + ((size_t)(b * Lv + c * LCv)) * Dv + d;
    float s0 = 0.f, s1 = 0.f, s2 = 0.f, s3 = 0.f;
#pragma unroll 4
    for (int i = 0; i < LCv; i += 4) {
        s0 += xp[(size_t)i * Dv];
        s1 += xp[(size_t)(i + 1) * Dv];
        s2 += xp[(size_t)(i + 2) * Dv];
        s3 += xp[(size_t)(i + 3) * Dv];
    }
    g_pctx[(size_t)bc * Dv + d] = (s0 + s1) + (s2 + s3);
}
// batched-load register-scan (MLP=NCv)
__global__ void ctx_p2() {
    int idx = blockIdx.x * blockDim.x + threadIdx.x;
    if (idx >= Bv * Dv) return;
    int b = idx / Dv, d = idx % Dv;
    float v[NCv];
#pragma unroll
    for (int c = 0; c < NCv; c++)
        v[c] = g_pctx[((size_t)(b * NCv + c)) * Dv + d];
    float run = 0.f;
#pragma unroll
    for (int c = 0; c < NCv; c++) { float t = v[c]; v[c] = run; run += t; }
#pragma unroll
    for (int c = 0; c < NCv; c++)
        g_pctx[((size_t)(b * NCv + c)) * Dv + d] = v[c];
}
__global__ void ctx_p3(const float* __restrict__ x) {
    int bc = blockIdx.x; int b = bc >> NC_SH, c = bc & NC_MASK;
    int d = blockIdx.y * 128 + threadIdx.x;
    const float* xp = x + ((size_t)(b * Lv + c * LCv)) * Dv + d;
    float s = g_pctx[(size_t)bc * Dv + d];
    for (int i = 0; i < LCv; i++) {
        int l = c * LCv + i;
        float xv = xp[(size_t)i * Dv];
        s += xv;
        size_t row = (size_t)(b * Lv + l);
        g_xcat[row * 1024 + d] = xv;
        g_xcat[row * 1024 + 512 + d] = s / (float)(l + 1);
    }
}

// ================= values*gate =================
__global__ void __launch_bounds__(256) vg_kernel(
    const float* __restrict__ x, const float* __restrict__ w_ve,
    const float* __restrict__ b_ve, const float* __restrict__ w_g,
    const float* __restrict__ b_g)
{
    __shared__ float sw[8 * 512];
    __shared__ float sg[512];
    int tid = threadIdx.x;
    for (int idx = tid; idx < 512 * 8; idx += 256) {
        int k = idx >> 3, v = idx & 7;
        sw[v * 512 + k] = w_ve[idx];
    }
    for (int idx = tid; idx < 512; idx += 256) sg[idx] = w_g[idx];
    __syncthreads();
    int lane = tid & 31, w = tid >> 5;
    int m = blockIdx.x * 8 + w;
    const float* xr = x + (size_t)m * 512;
    float acc[8] = {0, 0, 0, 0, 0, 0, 0, 0}, ag = 0.f;
    for (int j = 0; j < 16; j++) {
        int k = lane + 32 * j;
        float xk = xr[k];
#pragma unroll
        for (int v = 0; v < 8; v++) acc[v] += xk * sw[v * 512 + k];
        ag += xk * sg[k];
    }
#pragma unroll
    for (int o = 16; o; o >>= 1) {
#pragma unroll
        for (int v = 0; v < 8; v++) acc[v] += __shfl_xor_sync(0xffffffffu, acc[v], o);
        ag += __shfl_xor_sync(0xffffffffu, ag, o);
    }
    if (lane == 0) {
        float gate = 1.f / (1.f + expf(-(ag + b_g[0])));
        g_gate[m] = gate;
#pragma unroll
        for (int v = 0; v < 8; v++) g_gv[(size_t)m * 8 + v] = (acc[v] + b_ve[v]) * gate;
    }
}

// ================= mem1 scan + fused pos_ret (phi sincos inline) =================
__global__ void mem1_p1(const float* __restrict__ pos) {
    int bc = blockIdx.x; int b = bc >> NC_SH, c = bc & NC_MASK;
    int d = blockIdx.y * 128 + threadIdx.x;
    size_t base = ((size_t)(b * Lv + c * LCv)) * Dv + d;
    float sc = 0.f, ss = 0.f, sm = 0.f;
    for (int i = 0; i < LCv; i++) {
        int lg = c * LCv + i;
        float mag = g_mag[base + (size_t)i * Dv];
        float v1  = g_v1[base + (size_t)i * Dv];
        float w = mag * v1;
        float sphi, cphi;
        sincosf(pos[(size_t)lg * Dv + d], &sphi, &cphi);
        sc += w * cphi;
        ss += w * sphi;
        sm += mag;
    }
    size_t o = (size_t)bc * Dv + d;
    g_pmc[o] = sc; g_pms[o] = ss; g_pmm[o] = sm;
}
// batched-load register-scan over 3 arrays (selector on blockIdx.y)
__global__ void mem1_p2() {
    int idx = blockIdx.x * blockDim.x + threadIdx.x;
    if (idx >= Bv * Dv) return;
    int sel = blockIdx.y;
    float* arr = (sel == 0) ? g_pmc : ((sel == 1) ? g_pms : g_pmm);
    int b = idx / Dv, d = idx % Dv;
    float v[NCv];
#pragma unroll
    for (int c = 0; c < NCv; c++)
        v[c] = arr[((size_t)(b * NCv + c)) * Dv + d];
    float run = 0.f;
#pragma unroll
    for (int c = 0; c < NCv; c++) { float t = v[c]; v[c] = run; run += t; }
#pragma unroll
    for (int c = 0; c < NCv; c++)
        arr[((size_t)(b * NCv + c)) * Dv + d] = v[c];
}
__global__ void mem1_p3(const float* __restrict__ pos) {
    int bc = blockIdx.x; int b = bc >> NC_SH, c = bc & NC_MASK;
    int d = blockIdx.y * 128 + threadIdx.x;
    size_t base = ((size_t)(b * Lv + c * LCv)) * Dv + d;
    size_t po = (size_t)bc * Dv + d;
    float sc = g_pmc[po], ss = g_pms[po], sm = g_pmm[po];
    for (int i = 0; i < LCv; i++) {
        int lg = c * LCv + i;
        float mag = g_mag[base + (size_t)i * Dv];
        float v1  = g_v1[base + (size_t)i * Dv];
        float w = mag * v1;
        float pp = pos[(size_t)lg * Dv + d];
        float sphi, cphi;
        sincosf(pp, &sphi, &cphi);
        sc += w * cphi;
        ss += w * sphi;
        sm += mag;
        float ph = pp + g_qd[base + (size_t)i * Dv];
        float sq, cq;
        sincosf(ph, &sq, &cq);
        g_posret[base + (size_t)i * Dv] =
            (sc * cq + ss * sq) * rsqrtf(sm + 1e-8f) * INV_SQRT_D;
    }
}

// ================= kv phasor scan + retrieval =================
__global__ void __launch_bounds__(256) kv_p1() {
    __shared__ float s_csp[128], s_ssp[128], s_gv[8];
    int bc = blockIdx.x; int b = bc >> NC_SH, c = bc & NC_MASK;
    int tid = threadIdx.x;
    int v = tid & 7, p_base = (tid >> 3) * 4;
    float aC[4] = {0, 0, 0, 0}, aS[4] = {0, 0, 0, 0};
    float gs = 0.f;
    for (int i = 0; i < LCv; i++) {
        int m = b * Lv + c * LCv + i;
        if (tid < 128) s_csp[tid] = g_csp[(size_t)m * 128 + tid];
        else           s_ssp[tid - 128] = g_ssp[(size_t)m * 128 + (tid - 128)];
        if (tid < 8) s_gv[tid] = g_gv[(size_t)m * 8 + tid];
        if (tid == 0) gs += g_gate[m];
        __syncthreads();
        float gvv = s_gv[v];
#pragma unroll
        for (int j = 0; j < 4; j++) {
            aC[j] += s_csp[p_base + j] * gvv;
            aS[j] += s_ssp[p_base + j] * gvv;
        }
        __syncthreads();
    }
#pragma unroll
    for (int j = 0; j < 4; j++) {
        size_t o = (size_t)bc * 1024 + (size_t)(p_base + j) * 8 + v;
        g_pkc[o] = aC[j]; g_pks[o] = aS[j];
    }
    if (tid == 0) g_pg[bc] = gs;
}
// batched-load register-scan; sel via blockIdx.y; gate handled by block 0
__global__ void kv_p2() {
    int idx = blockIdx.x * blockDim.x + threadIdx.x;
    if (idx < Bv * Pv * Vv) {
        float* arr = blockIdx.y ? g_pks : g_pkc;
        int b = idx >> 10, pv = idx & 1023;
        float v[NCv];
#pragma unroll
        for (int c = 0; c < NCv; c++)
            v[c] = arr[((size_t)(b * NCv + c)) * 1024 + pv];
        float run = 0.f;
#pragma unroll
        for (int c = 0; c < NCv; c++) { float t = v[c]; v[c] = run; run += t; }
#pragma unroll
        for (int c = 0; c < NCv; c++)
            arr[((size_t)(b * NCv + c)) * 1024 + pv] = v[c];
    }
    if (blockIdx.x == 0 && blockIdx.y == 0 && idx < Bv) {
        float v[NCv];
#pragma unroll
        for (int c = 0; c < NCv; c++) v[c] = g_pg[(size_t)idx * NCv + c];
        float run = 0.f;
#pragma unroll
        for (int c = 0; c < NCv; c++) { float t = v[c]; v[c] = run; run += t; }
#pragma unroll
        for (int c = 0; c < NCv; c++) g_pg[(size_t)idx * NCv + c] = v[c];
    }
}
// fused: scan + retrieval + kv_out (writes ccat[:,512:1024])
__global__ void __launch_bounds__(256) kv_p3(
    const float* __restrict__ w_kv, const float* __restrict__ b_kv)
{
    __shared__ float s_csp[128], s_ssp[128], s_cqp[128], s_sqp[128], s_gv[8];
    __shared__ float s_r[64];
    __shared__ float s_kvr[8];
    __shared__ float s_wkv[8 * 512];
    __shared__ float s_bkv[512];
    int bc = blockIdx.x; int b = bc >> NC_SH, c = bc & NC_MASK;
    int tid = threadIdx.x;
    int v = tid & 7, p_base = (tid >> 3) * 4;
    for (int i = tid; i < 8 * 512; i += 256) s_wkv[i] = w_kv[i];
    for (int i = tid; i < 512; i += 256) s_bkv[i] = b_kv[i];
    float aC[4], aS[4];
#pragma unroll
    for (int j = 0; j < 4; j++) {
        size_t o = (size_t)bc * 1024 + (size_t)(p_base + j) * 8 + v;
        aC[j] = g_pkc[o]; aS[j] = g_pks[o];
    }
    float gsum = (tid == 0) ? g_pg[bc] : 0.f;
    __syncthreads();
    for (int i = 0; i < LCv; i++) {
        int m = b * Lv + c * LCv + i;
        if (tid < 128) {
            s_csp[tid] = g_csp[(size_t)m * 128 + tid];
            s_cqp[tid] = g_cqp[(size_t)m * 128 + tid];
        } else {
            int t = tid - 128;
            s_ssp[t] = g_ssp[(size_t)m * 128 + t];
            s_sqp[t] = g_sqp[(size_t)m * 128 + t];
        }
        if (tid < 8) s_gv[tid] = g_gv[(size_t)m * 8 + tid];
        __syncthreads();
        float gvv = s_gv[v];
        float pr = 0.f;
#pragma unroll
        for (int j = 0; j < 4; j++) {
            int p = p_base + j;
            aC[j] += s_csp[p] * gvv;
            aS[j] += s_ssp[p] * gvv;
            pr += s_cqp[p] * aC[j] + s_sqp[p] * aS[j];
        }
        pr += __shfl_xor_sync(0xffffffffu, pr, 8);
        pr += __shfl_xor_sync(0xffffffffu, pr, 16);
        if ((tid & 31) < 8) s_r[(tid >> 5) * 8 + (tid & 7)] = pr;
        if (tid == 0) gsum += g_gate[m];
        __syncthreads();
        if (tid < 8) {
            float accv = 0.f;
#pragma unroll
            for (int w = 0; w < 8; w++) accv += s_r[w * 8 + tid];
            float inv = rsqrtf(fmaxf(__shfl_sync(0x000000ffu, gsum, 0, 8), 1.0f));
            s_kvr[tid] = accv * inv * INV_SQRT_P;
        }
        __syncthreads();
        float k0 = s_kvr[0], k1 = s_kvr[1], k2 = s_kvr[2], k3 = s_kvr[3];
        float k4 = s_kvr[4], k5 = s_kvr[5], k6 = s_kvr[6], k7 = s_kvr[7];
#pragma unroll
        for (int h = 0; h < 2; h++) {
            int n = tid + h * 256;
            float o = s_bkv[n];
            o += k0 * s_wkv[n];
            o += k1 * s_wkv[512 + n];
            o += k2 * s_wkv[1024 + n];
            o += k3 * s_wkv[1536 + n];
            o += k4 * s_wkv[2048 + n];
            o += k5 * s_wkv[2560 + n];
            o += k6 * s_wkv[3072 + n];
            o += k7 * s_wkv[3584 + n];
            g_ccat[(size_t)m * 1024 + 512 + n] = o;
        }
        __syncthreads();
    }
}

// ================= LayerNorm =================
__global__ void __launch_bounds__(256) ln_kernel(
    const float* __restrict__ lng, const float* __restrict__ lnb)
{
    int m = blockIdx.x, tid = threadIdx.x;
    const float4* row = (const float4*)(g_ccat + (size_t)m * 1024);
    float4 val = row[tid];
    float s = val.x + val.y + val.z + val.w;
    float q = val.x * val.x + val.y * val.y + val.z * val.z + val.w * val.w;
#pragma unroll
    for (int o = 16; o; o >>= 1) {
        s += __shfl_xor_sync(0xffffffffu, s, o);
        q += __shfl_xor_sync(0xffffffffu, q, o);
    }
    __shared__ float ss[8], sq[8];
    __shared__ float smu, srs;
    if ((tid & 31) == 0) { ss[tid >> 5] = s; sq[tid >> 5] = q; }
    __syncthreads();
    if (tid == 0) {
        float S = 0.f, Q = 0.f;
#pragma unroll
        for (int w = 0; w < 8; w++) { S += ss[w]; Q += sq[w]; }
        float mu = S * (1.f / 1024.f);
        float var = Q * (1.f / 1024.f) - mu * mu;
        smu = mu; srs = rsqrtf(var + 1e-5f);
    }
    __syncthreads();
    float mu = smu, rs = srs;
    float4 g4 = ((const float4*)lng)[tid];
    float4 b4 = ((const float4*)lnb)[tid];
    float4 o;
    o.x = (val.x - mu) * rs * g4.x + b4.x;
    o.y = (val.y - mu) * rs * g4.y + b4.y;
    o.z = (val.z - mu) * rs * g4.z + b4.z;
    o.w = (val.w - mu) * rs * g4.w + b4.w;
    ((float4*)(g_ln + (size_t)m * 1024))[tid] = o;
}

// ================= launch =================
extern "C" void kernel_launch(void* const* d_in, const int* in_sizes, int n_in,
                              void* d_out, int out_size)
{
    const float* x    = (const float*)d_in[0];
    const float* pos  = (const float*)d_in[1];
    const float* ms   = (const float*)d_in[2];
    const float* w_v  = (const float*)d_in[3];
    const float* b_v  = (const float*)d_in[4];
    const float* w_o  = (const float*)d_in[5];
    const float* b_o  = (const float*)d_in[6];
    const float* w_m  = (const float*)d_in[7];
    const float* b_m  = (const float*)d_in[8];
    const float* w_q  = (const float*)d_in[9];
    const float* b_q  = (const float*)d_in[10];
    const float* w_ke = (const float*)d_in[11];
    const float* b_ke = (const float*)d_in[12];
    const float* w_ve = (const float*)d_in[13];
    const float* b_ve = (const float*)d_in[14];
    const float* w_s1 = (const float*)d_in[15];
    const float* b_s1 = (const float*)d_in[16];
    const float* w_s2 = (const float*)d_in[17];
    const float* b_s2 = (const float*)d_in[18];
    const float* w_g  = (const float*)d_in[19];
    const float* b_g  = (const float*)d_in[20];
    const float* w_kv = (const float*)d_in[21];
    const float* b_kv = (const float*)d_in[22];
    const float* lng  = (const float*)d_in[23];
    const float* lnb  = (const float*)d_in[24];
    const float* w_t1 = (const float*)d_in[25];
    const float* b_t1 = (const float*)d_in[26];
    const float* w_t2 = (const float*)d_in[27];
    const float* b_t2 = (const float*)d_in[28];
    float* out = (float*)d_out;

    float *p_xcat, *p_v1, *p_mag, *p_qd, *p_s1g, *p_posret, *p_ccat, *p_ln,
          *p_h1, *p_wt, *p_cqp, *p_sqp, *p_csp, *p_ssp, *p_bcat;
    cudaGetSymbolAddress((void**)&p_xcat, g_xcat);
    cudaGetSymbolAddress((void**)&p_v1, g_v1);
    cudaGetSymbolAddress((void**)&p_mag, g_mag);
    cudaGetSymbolAddress((void**)&p_qd, g_qd);
    cudaGetSymbolAddress((void**)&p_s1g, g_s1g);
    cudaGetSymbolAddress((void**)&p_posret, g_posret);
    cudaGetSymbolAddress((void**)&p_ccat, g_ccat);
    cudaGetSymbolAddress((void**)&p_ln, g_ln);
    cudaGetSymbolAddress((void**)&p_h1, g_h1);
    cudaGetSymbolAddress((void**)&p_wt, g_wt);
    cudaGetSymbolAddress((void**)&p_cqp, g_cqp);
    cudaGetSymbolAddress((void**)&p_sqp, g_sqp);
    cudaGetSymbolAddress((void**)&p_csp, g_csp);
    cudaGetSymbolAddress((void**)&p_ssp, g_ssp);
    cudaGetSymbolAddress((void**)&p_bcat, g_bcat);

    float* wt_proj = p_wt + WT_PROJ;
    float* wt_o    = p_wt + WT_O;
    float* wt_s1   = p_wt + WT_S1;
    float* wt_s2   = p_wt + WT_S2;
    float* wt_t1   = p_wt + WT_T1;
    float* wt_t2   = p_wt + WT_T2;

    const int SMEM = 2 * STAGE_F * 4;  // 73728 B -> 2 CTAs/SM
    cudaFuncSetAttribute(mma_gemm, cudaFuncAttributeMaxDynamicSharedMemorySize, SMEM);

    TTable tt;
    tt.src[0] = w_v;  tt.dst[0] = wt_proj;              tt.K[0] = 512;  tt.N[0] = 512;
    tt.src[1] = w_m;  tt.dst[1] = wt_proj + 512 * 512;  tt.K[1] = 512;  tt.N[1] = 512;
    tt.src[2] = w_q;  tt.dst[2] = wt_proj + 1024 * 512; tt.K[2] = 512;  tt.N[2] = 512;
    tt.src[3] = w_ke; tt.dst[3] = wt_proj + 1536 * 512; tt.K[3] = 512;  tt.N[3] = 128;
    tt.src[4] = w_o;  tt.dst[4] = wt_o;                 tt.K[4] = 512;  tt.N[4] = 512;
    tt.src[5] = w_s1; tt.dst[5] = wt_s1;                tt.K[5] = 1024; tt.N[5] = 512;
    tt.src[6] = w_s2; tt.dst[6] = wt_s2;                tt.K[6] = 512;  tt.N[6] = 128;
    tt.src[7] = w_t1; tt.dst[7] = wt_t1;                tt.K[7] = 1024; tt.N[7] = 1024;
    tt.src[8] = w_t2; tt.dst[8] = wt_t2;                tt.K[8] = 1024; tt.N[8] = 512;
    int acc = 0;
    for (int i = 0; i < 9; i++) {
        tt.t0[i] = acc;
        acc += (tt.K[i] >> 5) * (tt.N[i] >> 5);
    }
    transpose_all<<<acc, 256>>>(tt);
    bias_concat<<<7, 256>>>(b_v, b_m, b_q, b_ke);

    dim3 tb(256);
    dim3 gScan(Bv * NCv, Dv / 128);

    ctx_p1<<<gScan, 128>>>(x);
    ctx_p2<<<(Bv * Dv + 255) / 256, 256>>>();
    ctx_p3<<<gScan, 128>>>(x);

    // merged projections: v | mag | qd | ke-sincos
    mma_gemm<<<dim3(13, 128), tb, SMEM>>>(x, wt_proj, p_bcat,
        p_v1, p_mag, p_qd, p_cqp, p_sqp, 512, 512, 6, ms);
    vg_kernel<<<Mv / 8, 256>>>(x, w_ve, b_ve, w_g, b_g);
    mma_gemm<<<dim3(4, 128), tb, SMEM>>>(p_xcat, wt_s1, b_s1,
        p_s1g, nullptr, nullptr, nullptr, nullptr, 1024, 512, 2, nullptr);
    mma_gemm<<<dim3(1, 128), tb, SMEM>>>(p_s1g, wt_s2, b_s2,
        p_csp, p_ssp, nullptr, nullptr, nullptr, 512, 128, 5, nullptr);

    // mem1 scan + pos_out
    mem1_p1<<<gScan, 128>>>(pos);
    mem1_p2<<<dim3((Bv * Dv + 255) / 256, 3), 256>>>();
    mem1_p3<<<gScan, 128>>>(pos);
    mma_gemm<<<dim3(4, 128), tb, SMEM>>>(p_posret, wt_o, b_o,
        p_ccat, nullptr, nullptr, nullptr, nullptr, 512, 1024, 0, nullptr);

    // kv scan + retrieval + fused kv_out
    kv_p1<<<Bv * NCv, 256>>>();
    kv_p2<<<dim3((Bv * Pv * Vv + 255) / 256, 2), 256>>>();
    kv_p3<<<Bv * NCv, 256>>>(w_kv, b_kv);

    // LN + output MLP + residual
    ln_kernel<<<Mv, 256>>>(lng, lnb);
    mma_gemm<<<dim3(8, 128), tb, SMEM>>>(p_ln, wt_t1, b_t1,
        p_h1, nullptr, nullptr, nullptr, nullptr, 1024, 1024, 2, nullptr);
    mma_gemm<<<dim3(4, 128), tb, SMEM>>>(p_h1, wt_t2, b_t2,
        out, nullptr, nullptr, nullptr, nullptr, 1024, 512, 4, x);
}

// round 10
// speedup vs baseline: 1.2048x; 1.0491x over previous
#include <cuda_runtime.h>
#include <math.h>
#include <stdint.h>

#define Bv 4
#define Lv 4096
#define Dv 512
#define Pv 128
#define Vv 8
#define Mv (Bv*Lv)          // 16384
#define NCv 64
#define NC_SH 6
#define NC_MASK 63
#define LCv (Lv/NCv)        // 64
#define PI_F 3.14159265358979323846f
#define INV_SQRT_D 0.044194173824159216f
#define INV_SQRT_P 0.08838834764831845f

// ================= helpers =================
__device__ __forceinline__ uint32_t smem_u32(const void* p) {
    uint32_t a;
    asm("{ .reg .u64 t; cvta.to.shared.u64 t, %1; cvt.u32.u64 %0, t; }" : "=r"(a) : "l"(p));
    return a;
}
__device__ __forceinline__ void cp16(uint32_t s, const void* g) {
    asm volatile("cp.async.cg.shared.global [%0], [%1], 16;" :: "r"(s), "l"(g) : "memory");
}
#define CP_COMMIT() asm volatile("cp.async.commit_group;" ::: "memory")
#define CP_WAIT1()  asm volatile("cp.async.wait_group 1;" ::: "memory")
#define CP_WAIT0()  asm volatile("cp.async.wait_group 0;" ::: "memory")

__device__ __forceinline__ float f2tf32f(float v) {
    uint32_t u;
    asm("cvt.rna.tf32.f32 %0, %1;" : "=r"(u) : "f"(v));
    return __uint_as_float(u);
}
__device__ __forceinline__ void mma_tf32(float* c,
    uint32_t a0, uint32_t a1, uint32_t a2, uint32_t a3,
    uint32_t b0, uint32_t b1)
{
    asm volatile(
        "mma.sync.aligned.m16n8k8.row.col.f32.tf32.tf32.f32 "
        "{%0,%1,%2,%3}, {%4,%5,%6,%7}, {%8,%9}, {%0,%1,%2,%3};"
        : "+f"(c[0]), "+f"(c[1]), "+f"(c[2]), "+f"(c[3])
        : "r"(a0), "r"(a1), "r"(a2), "r"(a3), "r"(b0), "r"(b1));
}
__device__ __forceinline__ void ldmx4(uint32_t* r, uint32_t addr) {
    asm volatile(
        "ldmatrix.sync.aligned.m8n8.x4.shared.b16 {%0,%1,%2,%3}, [%4];"
        : "=r"(r[0]), "=r"(r[1]), "=r"(r[2]), "=r"(r[3]) : "r"(addr));
}

// ================= scratch =================
__device__ float g_xcat[(size_t)Mv*1024];
__device__ float g_v1[(size_t)Mv*512];
__device__ float g_mag[(size_t)Mv*512];
__device__ float g_qd[(size_t)Mv*512];
__device__ float g_cqp[(size_t)Mv*128], g_sqp[(size_t)Mv*128];
__device__ float g_csp[(size_t)Mv*128], g_ssp[(size_t)Mv*128];
__device__ float g_gv[(size_t)Mv*8], g_gate[Mv];
__device__ float g_s1g[(size_t)Mv*512];
__device__ float g_posret[(size_t)Mv*512];
__device__ float g_ccat[(size_t)Mv*1024];
__device__ float g_ln[(size_t)Mv*1024];
__device__ float g_h1[(size_t)Mv*1024];
__device__ float g_wt[3276800];
__device__ float g_bcat[1664];
__device__ float g_pctx[Bv*NCv*Dv];
__device__ float g_pmc[Bv*NCv*Dv], g_pms[Bv*NCv*Dv], g_pmm[Bv*NCv*Dv];
__device__ float g_pkc[Bv*NCv*Pv*Vv], g_pks[Bv*NCv*Pv*Vv], g_pg[Bv*NCv];

// arena offsets (floats)
#define WT_PROJ 0
#define WT_O    851968
#define WT_S1   1114112
#define WT_S2   1638400
#define WT_T1   1703936
#define WT_T2   2752512

// ================= batched transpose+tf32-round =================
struct TTable {
    const float* src[9];
    float* dst[9];
    int K[9], N[9], t0[9];
};
__global__ void __launch_bounds__(256) transpose_all(TTable tt) {
    __shared__ float t[32][33];
    int bid = blockIdx.x;
    int w = 8;
#pragma unroll
    for (int i = 8; i >= 0; i--) if (bid >= tt.t0[i]) { w = i; break; }
    int tl = bid - tt.t0[w];
    int K = tt.K[w], N = tt.N[w];
    int tilesK = K >> 5;
    int k0 = (tl % tilesK) * 32, n0 = (tl / tilesK) * 32;
    const float* W = tt.src[w];
    float* WT = tt.dst[w];
    int tx = threadIdx.x & 31, ty = threadIdx.x >> 5;
#pragma unroll
    for (int i = ty; i < 32; i += 8) t[i][tx] = W[(size_t)(k0 + i) * N + n0 + tx];
    __syncthreads();
#pragma unroll
    for (int i = ty; i < 32; i += 8)
        WT[(size_t)(n0 + i) * K + k0 + tx] = f2tf32f(t[tx][i]);
}

// ================= bias concat =================
__global__ void bias_concat(const float* b_v, const float* b_m,
                            const float* b_q, const float* b_ke) {
    int i = blockIdx.x * blockDim.x + threadIdx.x;
    if (i < 512)        g_bcat[i] = b_v[i];
    else if (i < 1024)  g_bcat[i] = b_m[i - 512];
    else if (i < 1536)  g_bcat[i] = b_q[i - 1024];
    else if (i < 1664)  g_bcat[i] = b_ke[i - 1536];
}

// ================= tf32 mma.sync GEMM (128x128, 2-stage, 2 CTAs/SM, ldmatrix) =================
// epi: 0 none, 1 sigmoid*|*eptr|, 2 exact gelu, 4 +eptr residual,
//      5 sincos(tanh*PI)->C,C2, 6 merged-proj (v1|mag|qd|ke-sincos)
#define LDA 36
#define STAGE_F (256 * LDA)
__global__ void __launch_bounds__(256, 2) mma_gemm(
    const float* __restrict__ A, const float* __restrict__ WT,
    const float* __restrict__ bias,
    float* __restrict__ C, float* __restrict__ C2, float* __restrict__ C3,
    float* __restrict__ C4, float* __restrict__ C5,
    int K, int ldc, int epi, const float* __restrict__ eptr)
{
    extern __shared__ float sm[];
    const int tid = threadIdx.x, wid = tid >> 5, lane = tid & 31;
    const int warp_m = wid & 3, warp_n = wid >> 2;   // 4 x 2
    const int n0 = blockIdx.x * 128, m0 = blockIdx.y * 128;
    const int NK = K >> 5;
    const int lq = lane >> 2, lr = lane & 3;

    // ldmatrix lane addressing: g = matrix id (0..3), r = row within matrix
    const int g = lane >> 3, r = lane & 7;
    // A fragment base (bytes, rel. to A-tile start), mi=0; mi=1 adds 16*LDA*4
    const uint32_t aoff = ((uint32_t)((warp_m * 32 + (g & 1) * 8 + r) * LDA
                           + (g >> 1) * 4)) * 4u;
    // B fragment base (bytes, rel. to B-tile start), jp=0; jp adds jp*16*LDA*4
    const uint32_t boff = ((uint32_t)((warp_n * 64 + (g >> 1) * 8 + r) * LDA
                           + (g & 1) * 4)) * 4u;

    const uint32_t sbase = smem_u32(sm);

    float c[2][8][4];
#pragma unroll
    for (int mi = 0; mi < 2; mi++)
#pragma unroll
        for (int j = 0; j < 8; j++)
#pragma unroll
            for (int q = 0; q < 4; q++) c[mi][j][q] = 0.f;

    auto load_tile = [&](int kt, int buf) {
        float* dst = sm + buf * STAGE_F;
#pragma unroll
        for (int i = 0; i < 4; i++) {
            int idx = tid + i * 256;
            int row = idx >> 3, cq = idx & 7;
            cp16(smem_u32(dst + row * LDA + cq * 4),
                 A + (size_t)(m0 + row) * K + kt * 32 + cq * 4);
        }
#pragma unroll
        for (int i = 0; i < 4; i++) {
            int idx = tid + i * 256;
            int row = idx >> 3, cq = idx & 7;
            cp16(smem_u32(dst + 128 * LDA + row * LDA + cq * 4),
                 WT + (size_t)(n0 + row) * K + kt * 32 + cq * 4);
        }
        CP_COMMIT();
    };

    load_tile(0, 0);

    for (int kt = 0; kt < NK; kt++) {
        int buf = kt & 1;
        if (kt + 1 < NK) load_tile(kt + 1, buf ^ 1);
        if (kt + 1 < NK) { CP_WAIT1(); } else { CP_WAIT0(); }
        __syncthreads();

        const uint32_t aBase = sbase + (uint32_t)(buf * STAGE_F) * 4u;
        const uint32_t bBase = aBase + 128u * LDA * 4u;
#pragma unroll
        for (int ks = 0; ks < 4; ks++) {
            uint32_t kbb = (uint32_t)ks * 32u;   // ks*8 floats in bytes
            uint32_t a[2][4];
            ldmx4(a[0], aBase + aoff + kbb);
            ldmx4(a[1], aBase + aoff + 16u * LDA * 4u + kbb);
#pragma unroll
            for (int jp = 0; jp < 4; jp++) {
                uint32_t bR[4];
                ldmx4(bR, bBase + boff + (uint32_t)jp * 16u * LDA * 4u + kbb);
                int j0 = jp * 2;
                mma_tf32(c[0][j0], a[0][0], a[0][1], a[0][2], a[0][3], bR[0], bR[1]);
                mma_tf32(c[1][j0], a[1][0], a[1][1], a[1][2], a[1][3], bR[0], bR[1]);
                mma_tf32(c[0][j0 + 1], a[0][0], a[0][1], a[0][2], a[0][3], bR[2], bR[3]);
                mma_tf32(c[1][j0 + 1], a[1][0], a[1][1], a[1][2], a[1][3], bR[2], bR[3]);
            }
        }
        __syncthreads();
    }

    // ---------------- epilogue ----------------
    float scale1 = (epi == 1 || epi == 6) ? fabsf(*eptr) : 0.f;
    int seg = n0 >> 9;
#pragma unroll
    for (int mi = 0; mi < 2; mi++) {
#pragma unroll
        for (int j = 0; j < 8; j++) {
            int gm = m0 + warp_m * 32 + mi * 16 + lq;
            int gn = n0 + warp_n * 64 + j * 8 + lr * 2;
            float b0 = bias[gn], b1 = bias[gn + 1];
#pragma unroll
            for (int h = 0; h < 2; h++) {
                int gmr = gm + h * 8;
                float v0 = c[mi][j][h * 2 + 0] + b0;
                float v1 = c[mi][j][h * 2 + 1] + b1;
                if (epi == 6) {
                    if (seg == 0) {
                        C[(size_t)gmr * 512 + gn] = v0;
                        C[(size_t)gmr * 512 + gn + 1] = v1;
                    } else if (seg == 1) {
                        size_t oo = (size_t)gmr * 512 + gn - 512;
                        C2[oo]     = scale1 / (1.f + expf(-v0));
                        C2[oo + 1] = scale1 / (1.f + expf(-v1));
                    } else if (seg == 2) {
                        size_t oo = (size_t)gmr * 512 + gn - 1024;
                        C3[oo] = v0; C3[oo + 1] = v1;
                    } else {
                        size_t oo = (size_t)gmr * 128 + gn - 1536;
                        float t0 = tanhf(v0) * PI_F, t1 = tanhf(v1) * PI_F;
                        float s0, cc0, s1, cc1;
                        sincosf(t0, &s0, &cc0);
                        sincosf(t1, &s1, &cc1);
                        C4[oo] = cc0; C4[oo + 1] = cc1;
                        C5[oo] = s0;  C5[oo + 1] = s1;
                    }
                    continue;
                }
                size_t oo = (size_t)gmr * ldc + gn;
                if (epi == 1) {
                    v0 = scale1 / (1.f + expf(-v0));
                    v1 = scale1 / (1.f + expf(-v1));
                } else if (epi == 2) {
                    v0 = 0.5f * v0 * (1.f + erff(v0 * 0.70710678118654752f));
                    v1 = 0.5f * v1 * (1.f + erff(v1 * 0.70710678118654752f));
                } else if (epi == 4) {
                    v0 += eptr[oo];
                    v1 += eptr[oo + 1];
                } else if (epi == 5) {
                    float t0 = tanhf(v0) * PI_F, t1 = tanhf(v1) * PI_F;
                    float s0, c0, s1, c1;
                    sincosf(t0, &s0, &c0);
                    sincosf(t1, &s1, &c1);
                    C[oo] = c0; C[oo + 1] = c1;
                    C2[oo] = s0; C2[oo + 1] = s1;
                    continue;
                }
                C[oo] = v0; C[oo + 1] = v1;
            }
        }
    }
}

// ================= context_avg scan =================
__global__ void ctx_p1(const float* __restrict__ x) {
    int bc = blockIdx.x; int b = bc >> NC_SH, c = bc & NC_MASK;
    int d = blockIdx.y * 128 + threadIdx.x;
    const float* xp = x + ((size_t)(b * Lv + c * LCv)) * Dv + d;
    float s0 = 0.f, s1 = 0.f, s2 = 0.f, s3 = 0.f;
#pragma unroll 4
    for (int i = 0; i < LCv; i += 4) {
        s0 += xp[(size_t)i * Dv];
        s1 += xp[(size_t)(i + 1) * Dv];
        s2 += xp[(size_t)(i + 2) * Dv];
        s3 += xp[(size_t)(i + 3) * Dv];
    }
    g_pctx[(size_t)bc * Dv + d] = (s0 + s1) + (s2 + s3);
}
__global__ void ctx_p2() {
    int idx = blockIdx.x * blockDim.x + threadIdx.x;
    if (idx >= Bv * Dv) return;
    int b = idx / Dv, d = idx % Dv;
    float v[NCv];
#pragma unroll
    for (int c = 0; c < NCv; c++)
        v[c] = g_pctx[((size_t)(b * NCv + c)) * Dv + d];
    float run = 0.f;
#pragma unroll
    for (int c = 0; c < NCv; c++) { float t = v[c]; v[c] = run; run += t; }
#pragma unroll
    for (int c = 0; c < NCv; c++)
        g_pctx[((size_t)(b * NCv + c)) * Dv + d] = v[c];
}
__global__ void ctx_p3(const float* __restrict__ x) {
    int bc = blockIdx.x; int b = bc >> NC_SH, c = bc & NC_MASK;
    int d = blockIdx.y * 128 + threadIdx.x;
    const float* xp = x + ((size_t)(b * Lv + c * LCv)) * Dv + d;
    float s = g_pctx[(size_t)bc * Dv + d];
    for (int i = 0; i < LCv; i++) {
        int l = c * LCv + i;
        float xv = xp[(size_t)i * Dv];
        s += xv;
        size_t row = (size_t)(b * Lv + l);
        g_xcat[row * 1024 + d] = xv;
        g_xcat[row * 1024 + 512 + d] = s / (float)(l + 1);
    }
}

// ================= values*gate =================
__global__ void __launch_bounds__(256) vg_kernel(
    const float* __restrict__ x, const float* __restrict__ w_ve,
    const float* __restrict__ b_ve, const float* __restrict__ w_g,
    const float* __restrict__ b_g)
{
    __shared__ float sw[8 * 512];
    __shared__ float sg[512];
    int tid = threadIdx.x;
    for (int idx = tid; idx < 512 * 8; idx += 256) {
        int k = idx >> 3, v = idx & 7;
        sw[v * 512 + k] = w_ve[idx];
    }
    for (int idx = tid; idx < 512; idx += 256) sg[idx] = w_g[idx];
    __syncthreads();
    int lane = tid & 31, w = tid >> 5;
    int m = blockIdx.x * 8 + w;
    const float* xr = x + (size_t)m * 512;
    float acc[8] = {0, 0, 0, 0, 0, 0, 0, 0}, ag = 0.f;
    for (int j = 0; j < 16; j++) {
        int k = lane + 32 * j;
        float xk = xr[k];
#pragma unroll
        for (int v = 0; v < 8; v++) acc[v] += xk * sw[v * 512 + k];
        ag += xk * sg[k];
    }
#pragma unroll
    for (int o = 16; o; o >>= 1) {
#pragma unroll
        for (int v = 0; v < 8; v++) acc[v] += __shfl_xor_sync(0xffffffffu, acc[v], o);
        ag += __shfl_xor_sync(0xffffffffu, ag, o);
    }
    if (lane == 0) {
        float gate = 1.f / (1.f + expf(-(ag + b_g[0])));
        g_gate[m] = gate;
#pragma unroll
        for (int v = 0; v < 8; v++) g_gv[(size_t)m * 8 + v] = (acc[v] + b_ve[v]) * gate;
    }
}

// ================= mem1 scan + fused pos_ret (phi sincos inline) =================
__global__ void mem1_p1(const float* __restrict__ pos) {
    int bc = blockIdx.x; int b = bc >> NC_SH, c = bc & NC_MASK;
    int d = blockIdx.y * 128 + threadIdx.x;
    size_t base = ((size_t)(b * Lv + c * LCv)) * Dv + d;
    float sc = 0.f, ss = 0.f, sm = 0.f;
    for (int i = 0; i < LCv; i++) {
        int lg = c * LCv + i;
        float mag = g_mag[base + (size_t)i * Dv];
        float v1  = g_v1[base + (size_t)i * Dv];
        float w = mag * v1;
        float sphi, cphi;
        sincosf(pos[(size_t)lg * Dv + d], &sphi, &cphi);
        sc += w * cphi;
        ss += w * sphi;
        sm += mag;
    }
    size_t o = (size_t)bc * Dv + d;
    g_pmc[o] = sc; g_pms[o] = ss; g_pmm[o] = sm;
}
__global__ void mem1_p2() {
    int idx = blockIdx.x * blockDim.x + threadIdx.x;
    if (idx >= Bv * Dv) return;
    int sel = blockIdx.y;
    float* arr = (sel == 0) ? g_pmc : ((sel == 1) ? g_pms : g_pmm);
    int b = idx / Dv, d = idx % Dv;
    float v[NCv];
#pragma unroll
    for (int c = 0; c < NCv; c++)
        v[c] = arr[((size_t)(b * NCv + c)) * Dv + d];
    float run = 0.f;
#pragma unroll
    for (int c = 0; c < NCv; c++) { float t = v[c]; v[c] = run; run += t; }
#pragma unroll
    for (int c = 0; c < NCv; c++)
        arr[((size_t)(b * NCv + c)) * Dv + d] = v[c];
}
__global__ void mem1_p3(const float* __restrict__ pos) {
    int bc = blockIdx.x; int b = bc >> NC_SH, c = bc & NC_MASK;
    int d = blockIdx.y * 128 + threadIdx.x;
    size_t base = ((size_t)(b * Lv + c * LCv)) * Dv + d;
    size_t po = (size_t)bc * Dv + d;
    float sc = g_pmc[po], ss = g_pms[po], sm = g_pmm[po];
    for (int i = 0; i < LCv; i++) {
        int lg = c * LCv + i;
        float mag = g_mag[base + (size_t)i * Dv];
        float v1  = g_v1[base + (size_t)i * Dv];
        float w = mag * v1;
        float pp = pos[(size_t)lg * Dv + d];
        float sphi, cphi;
        sincosf(pp, &sphi, &cphi);
        sc += w * cphi;
        ss += w * sphi;
        sm += mag;
        float ph = pp + g_qd[base + (size_t)i * Dv];
        float sq, cq;
        sincosf(ph, &sq, &cq);
        g_posret[base + (size_t)i * Dv] =
            (sc * cq + ss * sq) * rsqrtf(sm + 1e-8f) * INV_SQRT_D;
    }
}

// ================= kv phasor scan + retrieval =================
__global__ void __launch_bounds__(256) kv_p1() {
    __shared__ float s_csp[128], s_ssp[128], s_gv[8];
    int bc = blockIdx.x; int b = bc >> NC_SH, c = bc & NC_MASK;
    int tid = threadIdx.x;
    int v = tid & 7, p_base = (tid >> 3) * 4;
    float aC[4] = {0, 0, 0, 0}, aS[4] = {0, 0, 0, 0};
    float gs = 0.f;
    for (int i = 0; i < LCv; i++) {
        int m = b * Lv + c * LCv + i;
        if (tid < 128) s_csp[tid] = g_csp[(size_t)m * 128 + tid];
        else           s_ssp[tid - 128] = g_ssp[(size_t)m * 128 + (tid - 128)];
        if (tid < 8) s_gv[tid] = g_gv[(size_t)m * 8 + tid];
        if (tid == 0) gs += g_gate[m];
        __syncthreads();
        float gvv = s_gv[v];
#pragma unroll
        for (int j = 0; j < 4; j++) {
            aC[j] += s_csp[p_base + j] * gvv;
            aS[j] += s_ssp[p_base + j] * gvv;
        }
        __syncthreads();
    }
#pragma unroll
    for (int j = 0; j < 4; j++) {
        size_t o = (size_t)bc * 1024 + (size_t)(p_base + j) * 8 + v;
        g_pkc[o] = aC[j]; g_pks[o] = aS[j];
    }
    if (tid == 0) g_pg[bc] = gs;
}
__global__ void kv_p2() {
    int idx = blockIdx.x * blockDim.x + threadIdx.x;
    if (idx < Bv * Pv * Vv) {
        float* arr = blockIdx.y ? g_pks : g_pkc;
        int b = idx >> 10, pv = idx & 1023;
        float v[NCv];
#pragma unroll
        for (int c = 0; c < NCv; c++)
            v[c] = arr[((size_t)(b * NCv + c)) * 1024 + pv];
        float run = 0.f;
#pragma unroll
        for (int c = 0; c < NCv; c++) { float t = v[c]; v[c] = run; run += t; }
#pragma unroll
        for (int c = 0; c < NCv; c++)
            arr[((size_t)(b * NCv + c)) * 1024 + pv] = v[c];
    }
    if (blockIdx.x == 0 && blockIdx.y == 0 && idx < Bv) {
        float v[NCv];
#pragma unroll
        for (int c = 0; c < NCv; c++) v[c] = g_pg[(size_t)idx * NCv + c];
        float run = 0.f;
#pragma unroll
        for (int c = 0; c < NCv; c++) { float t = v[c]; v[c] = run; run += t; }
#pragma unroll
        for (int c = 0; c < NCv; c++) g_pg[(size_t)idx * NCv + c] = v[c];
    }
}
// fused: scan + retrieval + kv_out (writes ccat[:,512:1024])
__global__ void __launch_bounds__(256) kv_p3(
    const float* __restrict__ w_kv, const float* __restrict__ b_kv)
{
    __shared__ float s_csp[128], s_ssp[128], s_cqp[128], s_sqp[128], s_gv[8];
    __shared__ float s_r[64];
    __shared__ float s_kvr[8];
    __shared__ float s_wkv[8 * 512];
    __shared__ float s_bkv[512];
    int bc = blockIdx.x; int b = bc >> NC_SH, c = bc & NC_MASK;
    int tid = threadIdx.x;
    int v = tid & 7, p_base = (tid >> 3) * 4;
    for (int i = tid; i < 8 * 512; i += 256) s_wkv[i] = w_kv[i];
    for (int i = tid; i < 512; i += 256) s_bkv[i] = b_kv[i];
    float aC[4], aS[4];
#pragma unroll
    for (int j = 0; j < 4; j++) {
        size_t o = (size_t)bc * 1024 + (size_t)(p_base + j) * 8 + v;
        aC[j] = g_pkc[o]; aS[j] = g_pks[o];
    }
    float gsum = (tid == 0) ? g_pg[bc] : 0.f;
    __syncthreads();
    for (int i = 0; i < LCv; i++) {
        int m = b * Lv + c * LCv + i;
        if (tid < 128) {
            s_csp[tid] = g_csp[(size_t)m * 128 + tid];
            s_cqp[tid] = g_cqp[(size_t)m * 128 + tid];
        } else {
            int t = tid - 128;
            s_ssp[t] = g_ssp[(size_t)m * 128 + t];
            s_sqp[t] = g_sqp[(size_t)m * 128 + t];
        }
        if (tid < 8) s_gv[tid] = g_gv[(size_t)m * 8 + tid];
        __syncthreads();
        float gvv = s_gv[v];
        float pr = 0.f;
#pragma unroll
        for (int j = 0; j < 4; j++) {
            int p = p_base + j;
            aC[j] += s_csp[p] * gvv;
            aS[j] += s_ssp[p] * gvv;
            pr += s_cqp[p] * aC[j] + s_sqp[p] * aS[j];
        }
        pr += __shfl_xor_sync(0xffffffffu, pr, 8);
        pr += __shfl_xor_sync(0xffffffffu, pr, 16);
        if ((tid & 31) < 8) s_r[(tid >> 5) * 8 + (tid & 7)] = pr;
        if (tid == 0) gsum += g_gate[m];
        __syncthreads();
        if (tid < 8) {
            float accv = 0.f;
#pragma unroll
            for (int w = 0; w < 8; w++) accv += s_r[w * 8 + tid];
            float inv = rsqrtf(fmaxf(__shfl_sync(0x000000ffu, gsum, 0, 8), 1.0f));
            s_kvr[tid] = accv * inv * INV_SQRT_P;
        }
        __syncthreads();
        float k0 = s_kvr[0], k1 = s_kvr[1], k2 = s_kvr[2], k3 = s_kvr[3];
        float k4 = s_kvr[4], k5 = s_kvr[5], k6 = s_kvr[6], k7 = s_kvr[7];
#pragma unroll
        for (int h = 0; h < 2; h++) {
            int n = tid + h * 256;
            float o = s_bkv[n];
            o += k0 * s_wkv[n];
            o += k1 * s_wkv[512 + n];
            o += k2 * s_wkv[1024 + n];
            o += k3 * s_wkv[1536 + n];
            o += k4 * s_wkv[2048 + n];
            o += k5 * s_wkv[2560 + n];
            o += k6 * s_wkv[3072 + n];
            o += k7 * s_wkv[3584 + n];
            g_ccat[(size_t)m * 1024 + 512 + n] = o;
        }
        __syncthreads();
    }
}

// ================= LayerNorm =================
__global__ void __launch_bounds__(256) ln_kernel(
    const float* __restrict__ lng, const float* __restrict__ lnb)
{
    int m = blockIdx.x, tid = threadIdx.x;
    const float4* row = (const float4*)(g_ccat + (size_t)m * 1024);
    float4 val = row[tid];
    float s = val.x + val.y + val.z + val.w;
    float q = val.x * val.x + val.y * val.y + val.z * val.z + val.w * val.w;
#pragma unroll
    for (int o = 16; o; o >>= 1) {
        s += __shfl_xor_sync(0xffffffffu, s, o);
        q += __shfl_xor_sync(0xffffffffu, q, o);
    }
    __shared__ float ss[8], sq[8];
    __shared__ float smu, srs;
    if ((tid & 31) == 0) { ss[tid >> 5] = s; sq[tid >> 5] = q; }
    __syncthreads();
    if (tid == 0) {
        float S = 0.f, Q = 0.f;
#pragma unroll
        for (int w = 0; w < 8; w++) { S += ss[w]; Q += sq[w]; }
        float mu = S * (1.f / 1024.f);
        float var = Q * (1.f / 1024.f) - mu * mu;
        smu = mu; srs = rsqrtf(var + 1e-5f);
    }
    __syncthreads();
    float mu = smu, rs = srs;
    float4 g4 = ((const float4*)lng)[tid];
    float4 b4 = ((const float4*)lnb)[tid];
    float4 o;
    o.x = (val.x - mu) * rs * g4.x + b4.x;
    o.y = (val.y - mu) * rs * g4.y + b4.y;
    o.z = (val.z - mu) * rs * g4.z + b4.z;
    o.w = (val.w - mu) * rs * g4.w + b4.w;
    ((float4*)(g_ln + (size_t)m * 1024))[tid] = o;
}

// ================= launch =================
extern "C" void kernel_launch(void* const* d_in, const int* in_sizes, int n_in,
                              void* d_out, int out_size)
{
    const float* x    = (const float*)d_in[0];
    const float* pos  = (const float*)d_in[1];
    const float* ms   = (const float*)d_in[2];
    const float* w_v  = (const float*)d_in[3];
    const float* b_v  = (const float*)d_in[4];
    const float* w_o  = (const float*)d_in[5];
    const float* b_o  = (const float*)d_in[6];
    const float* w_m  = (const float*)d_in[7];
    const float* b_m  = (const float*)d_in[8];
    const float* w_q  = (const float*)d_in[9];
    const float* b_q  = (const float*)d_in[10];
    const float* w_ke = (const float*)d_in[11];
    const float* b_ke = (const float*)d_in[12];
    const float* w_ve = (const float*)d_in[13];
    const float* b_ve = (const float*)d_in[14];
    const float* w_s1 = (const float*)d_in[15];
    const float* b_s1 = (const float*)d_in[16];
    const float* w_s2 = (const float*)d_in[17];
    const float* b_s2 = (const float*)d_in[18];
    const float* w_g  = (const float*)d_in[19];
    const float* b_g  = (const float*)d_in[20];
    const float* w_kv = (const float*)d_in[21];
    const float* b_kv = (const float*)d_in[22];
    const float* lng  = (const float*)d_in[23];
    const float* lnb  = (const float*)d_in[24];
    const float* w_t1 = (const float*)d_in[25];
    const float* b_t1 = (const float*)d_in[26];
    const float* w_t2 = (const float*)d_in[27];
    const float* b_t2 = (const float*)d_in[28];
    float* out = (float*)d_out;

    float *p_xcat, *p_v1, *p_mag, *p_qd, *p_s1g, *p_posret, *p_ccat, *p_ln,
          *p_h1, *p_wt, *p_cqp, *p_sqp, *p_csp, *p_ssp, *p_bcat;
    cudaGetSymbolAddress((void**)&p_xcat, g_xcat);
    cudaGetSymbolAddress((void**)&p_v1, g_v1);
    cudaGetSymbolAddress((void**)&p_mag, g_mag);
    cudaGetSymbolAddress((void**)&p_qd, g_qd);
    cudaGetSymbolAddress((void**)&p_s1g, g_s1g);
    cudaGetSymbolAddress((void**)&p_posret, g_posret);
    cudaGetSymbolAddress((void**)&p_ccat, g_ccat);
    cudaGetSymbolAddress((void**)&p_ln, g_ln);
    cudaGetSymbolAddress((void**)&p_h1, g_h1);
    cudaGetSymbolAddress((void**)&p_wt, g_wt);
    cudaGetSymbolAddress((void**)&p_cqp, g_cqp);
    cudaGetSymbolAddress((void**)&p_sqp, g_sqp);
    cudaGetSymbolAddress((void**)&p_csp, g_csp);
    cudaGetSymbolAddress((void**)&p_ssp, g_ssp);
    cudaGetSymbolAddress((void**)&p_bcat, g_bcat);

    float* wt_proj = p_wt + WT_PROJ;
    float* wt_o    = p_wt + WT_O;
    float* wt_s1   = p_wt + WT_S1;
    float* wt_s2   = p_wt + WT_S2;
    float* wt_t1   = p_wt + WT_T1;
    float* wt_t2   = p_wt + WT_T2;

    const int SMEM = 2 * STAGE_F * 4;  // 73728 B -> 2 CTAs/SM
    cudaFuncSetAttribute(mma_gemm, cudaFuncAttributeMaxDynamicSharedMemorySize, SMEM);

    TTable tt;
    tt.src[0] = w_v;  tt.dst[0] = wt_proj;              tt.K[0] = 512;  tt.N[0] = 512;
    tt.src[1] = w_m;  tt.dst[1] = wt_proj + 512 * 512;  tt.K[1] = 512;  tt.N[1] = 512;
    tt.src[2] = w_q;  tt.dst[2] = wt_proj + 1024 * 512; tt.K[2] = 512;  tt.N[2] = 512;
    tt.src[3] = w_ke; tt.dst[3] = wt_proj + 1536 * 512; tt.K[3] = 512;  tt.N[3] = 128;
    tt.src[4] = w_o;  tt.dst[4] = wt_o;                 tt.K[4] = 512;  tt.N[4] = 512;
    tt.src[5] = w_s1; tt.dst[5] = wt_s1;                tt.K[5] = 1024; tt.N[5] = 512;
    tt.src[6] = w_s2; tt.dst[6] = wt_s2;                tt.K[6] = 512;  tt.N[6] = 128;
    tt.src[7] = w_t1; tt.dst[7] = wt_t1;                tt.K[7] = 1024; tt.N[7] = 1024;
    tt.src[8] = w_t2; tt.dst[8] = wt_t2;                tt.K[8] = 1024; tt.N[8] = 512;
    int acc = 0;
    for (int i = 0; i < 9; i++) {
        tt.t0[i] = acc;
        acc += (tt.K[i] >> 5) * (tt.N[i] >> 5);
    }
    transpose_all<<<acc, 256>>>(tt);
    bias_concat<<<7, 256>>>(b_v, b_m, b_q, b_ke);

    dim3 tb(256);
    dim3 gScan(Bv * NCv, Dv / 128);

    ctx_p1<<<gScan, 128>>>(x);
    ctx_p2<<<(Bv * Dv + 255) / 256, 256>>>();
    ctx_p3<<<gScan, 128>>>(x);

    // merged projections: v | mag | qd | ke-sincos
    mma_gemm<<<dim3(13, 128), tb, SMEM>>>(x, wt_proj, p_bcat,
        p_v1, p_mag, p_qd, p_cqp, p_sqp, 512, 512, 6, ms);
    vg_kernel<<<Mv / 8, 256>>>(x, w_ve, b_ve, w_g, b_g);
    mma_gemm<<<dim3(4, 128), tb, SMEM>>>(p_xcat, wt_s1, b_s1,
        p_s1g, nullptr, nullptr, nullptr, nullptr, 1024, 512, 2, nullptr);
    mma_gemm<<<dim3(1, 128), tb, SMEM>>>(p_s1g, wt_s2, b_s2,
        p_csp, p_ssp, nullptr, nullptr, nullptr, 512, 128, 5, nullptr);

    // mem1 scan + pos_out
    mem1_p1<<<gScan, 128>>>(pos);
    mem1_p2<<<dim3((Bv * Dv + 255) / 256, 3), 256>>>();
    mem1_p3<<<gScan, 128>>>(pos);
    mma_gemm<<<dim3(4, 128), tb, SMEM>>>(p_posret, wt_o, b_o,
        p_ccat, nullptr, nullptr, nullptr, nullptr, 512, 1024, 0, nullptr);

    // kv scan + retrieval + fused kv_out
    kv_p1<<<Bv * NCv, 256>>>();
    kv_p2<<<dim3((Bv * Pv * Vv + 255) / 256, 2), 256>>>();
    kv_p3<<<Bv * NCv, 256>>>(w_kv, b_kv);

    // LN + output MLP + residual
    ln_kernel<<<Mv, 256>>>(lng, lnb);
    mma_gemm<<<dim3(8, 128), tb, SMEM>>>(p_ln, wt_t1, b_t1,
        p_h1, nullptr, nullptr, nullptr, nullptr, 1024, 1024, 2, nullptr);
    mma_gemm<<<dim3(4, 128), tb, SMEM>>>(p_h1, wt_t2, b_t2,
        out, nullptr, nullptr, nullptr, nullptr, 1024, 512, 4, x);
}

// round 11
// speedup vs baseline: 1.2965x; 1.0761x over previous
#include <cuda_runtime.h>
#include <math.h>
#include <stdint.h>

#define Bv 4
#define Lv 4096
#define Dv 512
#define Pv 128
#define Vv 8
#define Mv (Bv*Lv)          // 16384
#define NCv 64
#define NC_SH 6
#define NC_MASK 63
#define LCv (Lv/NCv)        // 64
#define PI_F 3.14159265358979323846f
#define INV_SQRT_D 0.044194173824159216f
#define INV_SQRT_P 0.08838834764831845f

// ================= helpers =================
__device__ __forceinline__ uint32_t smem_u32(const void* p) {
    uint32_t a;
    asm("{ .reg .u64 t; cvta.to.shared.u64 t, %1; cvt.u32.u64 %0, t; }" : "=r"(a) : "l"(p));
    return a;
}
__device__ __forceinline__ void cp16(uint32_t s, const void* g) {
    asm volatile("cp.async.cg.shared.global [%0], [%1], 16;" :: "r"(s), "l"(g) : "memory");
}
#define CP_COMMIT() asm volatile("cp.async.commit_group;" ::: "memory")
#define CP_WAIT1()  asm volatile("cp.async.wait_group 1;" ::: "memory")
#define CP_WAIT0()  asm volatile("cp.async.wait_group 0;" ::: "memory")

__device__ __forceinline__ float f2tf32f(float v) {
    uint32_t u;
    asm("cvt.rna.tf32.f32 %0, %1;" : "=r"(u) : "f"(v));
    return __uint_as_float(u);
}
__device__ __forceinline__ void mma_tf32(float* c,
    uint32_t a0, uint32_t a1, uint32_t a2, uint32_t a3,
    uint32_t b0, uint32_t b1)
{
    asm volatile(
        "mma.sync.aligned.m16n8k8.row.col.f32.tf32.tf32.f32 "
        "{%0,%1,%2,%3}, {%4,%5,%6,%7}, {%8,%9}, {%0,%1,%2,%3};"
        : "+f"(c[0]), "+f"(c[1]), "+f"(c[2]), "+f"(c[3])
        : "r"(a0), "r"(a1), "r"(a2), "r"(a3), "r"(b0), "r"(b1));
}
__device__ __forceinline__ void ldmx4(uint32_t* r, uint32_t addr) {
    asm volatile(
        "ldmatrix.sync.aligned.m8n8.x4.shared.b16 {%0,%1,%2,%3}, [%4];"
        : "=r"(r[0]), "=r"(r[1]), "=r"(r[2]), "=r"(r[3]) : "r"(addr));
}

// ================= scratch =================
__device__ float g_xcat[(size_t)Mv*1024];
__device__ float g_v1[(size_t)Mv*512];
__device__ float g_mag[(size_t)Mv*512];
__device__ float g_qd[(size_t)Mv*512];
__device__ float g_cqp[(size_t)Mv*128], g_sqp[(size_t)Mv*128];
__device__ float g_csp[(size_t)Mv*128], g_ssp[(size_t)Mv*128];
__device__ float g_gv[(size_t)Mv*8], g_gate[Mv];
__device__ float g_s1g[(size_t)Mv*512];
__device__ float g_posret[(size_t)Mv*512];
__device__ float g_ccat[(size_t)Mv*1024];
__device__ float g_ln[(size_t)Mv*1024];
__device__ float g_h1[(size_t)Mv*1024];
__device__ float g_wt[3276800];
__device__ float g_bcat[1664];
__device__ float g_pctx[Bv*NCv*Dv];
__device__ float g_pmc[Bv*NCv*Dv], g_pms[Bv*NCv*Dv], g_pmm[Bv*NCv*Dv];
__device__ float g_pkc[Bv*NCv*Pv*Vv], g_pks[Bv*NCv*Pv*Vv], g_pg[Bv*NCv];

// arena offsets (floats)
#define WT_PROJ 0
#define WT_O    851968
#define WT_S1   1114112
#define WT_S2   1638400
#define WT_T1   1703936
#define WT_T2   2752512

// ================= batched transpose+tf32-round =================
struct TTable {
    const float* src[9];
    float* dst[9];
    int K[9], N[9], t0[9];
};
__global__ void __launch_bounds__(256) transpose_all(TTable tt) {
    __shared__ float t[32][33];
    int bid = blockIdx.x;
    int w = 8;
#pragma unroll
    for (int i = 8; i >= 0; i--) if (bid >= tt.t0[i]) { w = i; break; }
    int tl = bid - tt.t0[w];
    int K = tt.K[w], N = tt.N[w];
    int tilesK = K >> 5;
    int k0 = (tl % tilesK) * 32, n0 = (tl / tilesK) * 32;
    const float* W = tt.src[w];
    float* WT = tt.dst[w];
    int tx = threadIdx.x & 31, ty = threadIdx.x >> 5;
#pragma unroll
    for (int i = ty; i < 32; i += 8) t[i][tx] = W[(size_t)(k0 + i) * N + n0 + tx];
    __syncthreads();
#pragma unroll
    for (int i = ty; i < 32; i += 8)
        WT[(size_t)(n0 + i) * K + k0 + tx] = f2tf32f(t[tx][i]);
}

// ================= bias concat =================
__global__ void bias_concat(const float* b_v, const float* b_m,
                            const float* b_q, const float* b_ke) {
    int i = blockIdx.x * blockDim.x + threadIdx.x;
    if (i < 512)        g_bcat[i] = b_v[i];
    else if (i < 1024)  g_bcat[i] = b_m[i - 512];
    else if (i < 1536)  g_bcat[i] = b_q[i - 1024];
    else if (i < 1664)  g_bcat[i] = b_ke[i - 1536];
}

// ================= tf32 mma.sync GEMM (128x128, 2-stage, 2 CTAs/SM, ldmatrix) =================
// epi: 0 none, 1 sigmoid*|*eptr|, 2 exact gelu, 4 +eptr residual,
//      5 sincos(tanh*PI)->C,C2, 6 merged-proj (v1|mag|qd|ke-sincos)
#define LDA 36
#define STAGE_F (256 * LDA)
__global__ void __launch_bounds__(256, 2) mma_gemm(
    const float* __restrict__ A, const float* __restrict__ WT,
    const float* __restrict__ bias,
    float* __restrict__ C, float* __restrict__ C2, float* __restrict__ C3,
    float* __restrict__ C4, float* __restrict__ C5,
    int K, int ldc, int epi, const float* __restrict__ eptr)
{
    extern __shared__ float sm[];
    const int tid = threadIdx.x, wid = tid >> 5, lane = tid & 31;
    const int warp_m = wid & 3, warp_n = wid >> 2;   // 4 x 2
    const int n0 = blockIdx.x * 128, m0 = blockIdx.y * 128;
    const int NK = K >> 5;
    const int lq = lane >> 2, lr = lane & 3;

    const int g = lane >> 3, r = lane & 7;
    const uint32_t aoff = ((uint32_t)((warp_m * 32 + (g & 1) * 8 + r) * LDA
                           + (g >> 1) * 4)) * 4u;
    const uint32_t boff = ((uint32_t)((warp_n * 64 + (g >> 1) * 8 + r) * LDA
                           + (g & 1) * 4)) * 4u;

    const uint32_t sbase = smem_u32(sm);

    float c[2][8][4];
#pragma unroll
    for (int mi = 0; mi < 2; mi++)
#pragma unroll
        for (int j = 0; j < 8; j++)
#pragma unroll
            for (int q = 0; q < 4; q++) c[mi][j][q] = 0.f;

    auto load_tile = [&](int kt, int buf) {
        float* dst = sm + buf * STAGE_F;
#pragma unroll
        for (int i = 0; i < 4; i++) {
            int idx = tid + i * 256;
            int row = idx >> 3, cq = idx & 7;
            cp16(smem_u32(dst + row * LDA + cq * 4),
                 A + (size_t)(m0 + row) * K + kt * 32 + cq * 4);
        }
#pragma unroll
        for (int i = 0; i < 4; i++) {
            int idx = tid + i * 256;
            int row = idx >> 3, cq = idx & 7;
            cp16(smem_u32(dst + 128 * LDA + row * LDA + cq * 4),
                 WT + (size_t)(n0 + row) * K + kt * 32 + cq * 4);
        }
        CP_COMMIT();
    };

    load_tile(0, 0);

    for (int kt = 0; kt < NK; kt++) {
        int buf = kt & 1;
        if (kt + 1 < NK) load_tile(kt + 1, buf ^ 1);
        if (kt + 1 < NK) { CP_WAIT1(); } else { CP_WAIT0(); }
        __syncthreads();

        const uint32_t aBase = sbase + (uint32_t)(buf * STAGE_F) * 4u;
        const uint32_t bBase = aBase + 128u * LDA * 4u;
#pragma unroll
        for (int ks = 0; ks < 4; ks++) {
            uint32_t kbb = (uint32_t)ks * 32u;
            uint32_t a[2][4];
            ldmx4(a[0], aBase + aoff + kbb);
            ldmx4(a[1], aBase + aoff + 16u * LDA * 4u + kbb);
#pragma unroll
            for (int jp = 0; jp < 4; jp++) {
                uint32_t bR[4];
                ldmx4(bR, bBase + boff + (uint32_t)jp * 16u * LDA * 4u + kbb);
                int j0 = jp * 2;
                mma_tf32(c[0][j0], a[0][0], a[0][1], a[0][2], a[0][3], bR[0], bR[1]);
                mma_tf32(c[1][j0], a[1][0], a[1][1], a[1][2], a[1][3], bR[0], bR[1]);
                mma_tf32(c[0][j0 + 1], a[0][0], a[0][1], a[0][2], a[0][3], bR[2], bR[3]);
                mma_tf32(c[1][j0 + 1], a[1][0], a[1][1], a[1][2], a[1][3], bR[2], bR[3]);
            }
        }
        __syncthreads();
    }

    // ---------------- epilogue ----------------
    float scale1 = (epi == 1 || epi == 6) ? fabsf(*eptr) : 0.f;
    int seg = n0 >> 9;
#pragma unroll
    for (int mi = 0; mi < 2; mi++) {
#pragma unroll
        for (int j = 0; j < 8; j++) {
            int gm = m0 + warp_m * 32 + mi * 16 + lq;
            int gn = n0 + warp_n * 64 + j * 8 + lr * 2;
            float b0 = bias[gn], b1 = bias[gn + 1];
#pragma unroll
            for (int h = 0; h < 2; h++) {
                int gmr = gm + h * 8;
                float v0 = c[mi][j][h * 2 + 0] + b0;
                float v1 = c[mi][j][h * 2 + 1] + b1;
                if (epi == 6) {
                    if (seg == 0) {
                        C[(size_t)gmr * 512 + gn] = v0;
                        C[(size_t)gmr * 512 + gn + 1] = v1;
                    } else if (seg == 1) {
                        size_t oo = (size_t)gmr * 512 + gn - 512;
                        C2[oo]     = scale1 / (1.f + expf(-v0));
                        C2[oo + 1] = scale1 / (1.f + expf(-v1));
                    } else if (seg == 2) {
                        size_t oo = (size_t)gmr * 512 + gn - 1024;
                        C3[oo] = v0; C3[oo + 1] = v1;
                    } else {
                        size_t oo = (size_t)gmr * 128 + gn - 1536;
                        float t0 = tanhf(v0) * PI_F, t1 = tanhf(v1) * PI_F;
                        float s0, cc0, s1, cc1;
                        sincosf(t0, &s0, &cc0);
                        sincosf(t1, &s1, &cc1);
                        C4[oo] = cc0; C4[oo + 1] = cc1;
                        C5[oo] = s0;  C5[oo + 1] = s1;
                    }
                    continue;
                }
                size_t oo = (size_t)gmr * ldc + gn;
                if (epi == 1) {
                    v0 = scale1 / (1.f + expf(-v0));
                    v1 = scale1 / (1.f + expf(-v1));
                } else if (epi == 2) {
                    v0 = 0.5f * v0 * (1.f + erff(v0 * 0.70710678118654752f));
                    v1 = 0.5f * v1 * (1.f + erff(v1 * 0.70710678118654752f));
                } else if (epi == 4) {
                    v0 += eptr[oo];
                    v1 += eptr[oo + 1];
                } else if (epi == 5) {
                    float t0 = tanhf(v0) * PI_F, t1 = tanhf(v1) * PI_F;
                    float s0, c0, s1, c1;
                    sincosf(t0, &s0, &c0);
                    sincosf(t1, &s1, &c1);
                    C[oo] = c0; C[oo + 1] = c1;
                    C2[oo] = s0; C2[oo + 1] = s1;
                    continue;
                }
                C[oo] = v0; C[oo + 1] = v1;
            }
        }
    }
}

// ================= context_avg scan =================
__global__ void ctx_p1(const float* __restrict__ x) {
    int bc = blockIdx.x; int b = bc >> NC_SH, c = bc & NC_MASK;
    int d = blockIdx.y * 128 + threadIdx.x;
    const float* xp = x + ((size_t)(b * Lv + c * LCv)) * Dv + d;
    float s0 = 0.f, s1 = 0.f, s2 = 0.f, s3 = 0.f;
#pragma unroll 4
    for (int i = 0; i < LCv; i += 4) {
        s0 += xp[(size_t)i * Dv];
        s1 += xp[(size_t)(i + 1) * Dv];
        s2 += xp[(size_t)(i + 2) * Dv];
        s3 += xp[(size_t)(i + 3) * Dv];
    }
    g_pctx[(size_t)bc * Dv + d] = (s0 + s1) + (s2 + s3);
}
__global__ void ctx_p2() {
    int idx = blockIdx.x * blockDim.x + threadIdx.x;
    if (idx >= Bv * Dv) return;
    int b = idx / Dv, d = idx % Dv;
    float v[NCv];
#pragma unroll
    for (int c = 0; c < NCv; c++)
        v[c] = g_pctx[((size_t)(b * NCv + c)) * Dv + d];
    float run = 0.f;
#pragma unroll
    for (int c = 0; c < NCv; c++) { float t = v[c]; v[c] = run; run += t; }
#pragma unroll
    for (int c = 0; c < NCv; c++)
        g_pctx[((size_t)(b * NCv + c)) * Dv + d] = v[c];
}
__global__ void ctx_p3(const float* __restrict__ x) {
    int bc = blockIdx.x; int b = bc >> NC_SH, c = bc & NC_MASK;
    int d = blockIdx.y * 128 + threadIdx.x;
    const float* xp = x + ((size_t)(b * Lv + c * LCv)) * Dv + d;
    float s = g_pctx[(size_t)bc * Dv + d];
    for (int i = 0; i < LCv; i++) {
        int l = c * LCv + i;
        float xv = xp[(size_t)i * Dv];
        s += xv;
        size_t row = (size_t)(b * Lv + l);
        g_xcat[row * 1024 + d] = xv;
        g_xcat[row * 1024 + 512 + d] = s / (float)(l + 1);
    }
}

// ================= values*gate =================
__global__ void __launch_bounds__(256) vg_kernel(
    const float* __restrict__ x, const float* __restrict__ w_ve,
    const float* __restrict__ b_ve, const float* __restrict__ w_g,
    const float* __restrict__ b_g)
{
    __shared__ float sw[8 * 512];
    __shared__ float sg[512];
    int tid = threadIdx.x;
    for (int idx = tid; idx < 512 * 8; idx += 256) {
        int k = idx >> 3, v = idx & 7;
        sw[v * 512 + k] = w_ve[idx];
    }
    for (int idx = tid; idx < 512; idx += 256) sg[idx] = w_g[idx];
    __syncthreads();
    int lane = tid & 31, w = tid >> 5;
    int m = blockIdx.x * 8 + w;
    const float* xr = x + (size_t)m * 512;
    float acc[8] = {0, 0, 0, 0, 0, 0, 0, 0}, ag = 0.f;
    for (int j = 0; j < 16; j++) {
        int k = lane + 32 * j;
        float xk = xr[k];
#pragma unroll
        for (int v = 0; v < 8; v++) acc[v] += xk * sw[v * 512 + k];
        ag += xk * sg[k];
    }
#pragma unroll
    for (int o = 16; o; o >>= 1) {
#pragma unroll
        for (int v = 0; v < 8; v++) acc[v] += __shfl_xor_sync(0xffffffffu, acc[v], o);
        ag += __shfl_xor_sync(0xffffffffu, ag, o);
    }
    if (lane == 0) {
        float gate = 1.f / (1.f + expf(-(ag + b_g[0])));
        g_gate[m] = gate;
#pragma unroll
        for (int v = 0; v < 8; v++) g_gv[(size_t)m * 8 + v] = (acc[v] + b_ve[v]) * gate;
    }
}

// ================= mem1 scan + fused pos_ret (phi sincos inline) =================
__global__ void mem1_p1(const float* __restrict__ pos) {
    int bc = blockIdx.x; int b = bc >> NC_SH, c = bc & NC_MASK;
    int d = blockIdx.y * 128 + threadIdx.x;
    size_t base = ((size_t)(b * Lv + c * LCv)) * Dv + d;
    float sc = 0.f, ss = 0.f, sm = 0.f;
    for (int i = 0; i < LCv; i++) {
        int lg = c * LCv + i;
        float mag = g_mag[base + (size_t)i * Dv];
        float v1  = g_v1[base + (size_t)i * Dv];
        float w = mag * v1;
        float sphi, cphi;
        sincosf(pos[(size_t)lg * Dv + d], &sphi, &cphi);
        sc += w * cphi;
        ss += w * sphi;
        sm += mag;
    }
    size_t o = (size_t)bc * Dv + d;
    g_pmc[o] = sc; g_pms[o] = ss; g_pmm[o] = sm;
}
__global__ void mem1_p2() {
    int idx = blockIdx.x * blockDim.x + threadIdx.x;
    if (idx >= Bv * Dv) return;
    int sel = blockIdx.y;
    float* arr = (sel == 0) ? g_pmc : ((sel == 1) ? g_pms : g_pmm);
    int b = idx / Dv, d = idx % Dv;
    float v[NCv];
#pragma unroll
    for (int c = 0; c < NCv; c++)
        v[c] = arr[((size_t)(b * NCv + c)) * Dv + d];
    float run = 0.f;
#pragma unroll
    for (int c = 0; c < NCv; c++) { float t = v[c]; v[c] = run; run += t; }
#pragma unroll
    for (int c = 0; c < NCv; c++)
        arr[((size_t)(b * NCv + c)) * Dv + d] = v[c];
}
__global__ void mem1_p3(const float* __restrict__ pos) {
    int bc = blockIdx.x; int b = bc >> NC_SH, c = bc & NC_MASK;
    int d = blockIdx.y * 128 + threadIdx.x;
    size_t base = ((size_t)(b * Lv + c * LCv)) * Dv + d;
    size_t po = (size_t)bc * Dv + d;
    float sc = g_pmc[po], ss = g_pms[po], sm = g_pmm[po];
    for (int i = 0; i < LCv; i++) {
        int lg = c * LCv + i;
        float mag = g_mag[base + (size_t)i * Dv];
        float v1  = g_v1[base + (size_t)i * Dv];
        float w = mag * v1;
        float pp = pos[(size_t)lg * Dv + d];
        float sphi, cphi;
        sincosf(pp, &sphi, &cphi);
        sc += w * cphi;
        ss += w * sphi;
        sm += mag;
        float ph = pp + g_qd[base + (size_t)i * Dv];
        float sq, cq;
        sincosf(ph, &sq, &cq);
        g_posret[base + (size_t)i * Dv] =
            (sc * cq + ss * sq) * rsqrtf(sm + 1e-8f) * INV_SQRT_D;
    }
}

// ================= kv phasor scan: 8-token chunked, warp-per-v =================
// warp w owns v=w; lane l owns p=4l..4l+3.
__global__ void __launch_bounds__(256) kv_p1() {
    __shared__ float s_csp[8][128], s_ssp[8][128];
    __shared__ float s_gv[8][8], s_gate[8];
    int bc = blockIdx.x; int b = bc >> NC_SH, c = bc & NC_MASK;
    int tid = threadIdx.x, w = tid >> 5, l = tid & 31;
    int mbase = b * Lv + c * LCv;
    float aC[4] = {0, 0, 0, 0}, aS[4] = {0, 0, 0, 0};
    float gs = 0.f;
    for (int r0 = 0; r0 < LCv; r0 += 8) {
#pragma unroll
        for (int e = tid; e < 1024; e += 256) {
            int i = e >> 7, p = e & 127;
            size_t mm = (size_t)(mbase + r0 + i) * 128 + p;
            s_csp[i][p] = g_csp[mm];
            s_ssp[i][p] = g_ssp[mm];
        }
        if (tid < 64) s_gv[tid >> 3][tid & 7] = g_gv[(size_t)(mbase + r0 + (tid >> 3)) * 8 + (tid & 7)];
        if (tid < 8) s_gate[tid] = g_gate[mbase + r0 + tid];
        __syncthreads();
#pragma unroll
        for (int i = 0; i < 8; i++) {
            float gvv = s_gv[i][w];
            float4 cv = ((const float4*)s_csp[i])[l];
            float4 sv = ((const float4*)s_ssp[i])[l];
            aC[0] += cv.x * gvv; aC[1] += cv.y * gvv;
            aC[2] += cv.z * gvv; aC[3] += cv.w * gvv;
            aS[0] += sv.x * gvv; aS[1] += sv.y * gvv;
            aS[2] += sv.z * gvv; aS[3] += sv.w * gvv;
            gs += s_gate[i];
        }
        __syncthreads();
    }
#pragma unroll
    for (int j = 0; j < 4; j++) {
        size_t o = (size_t)bc * 1024 + (size_t)(4 * l + j) * 8 + w;
        g_pkc[o] = aC[j]; g_pks[o] = aS[j];
    }
    if (tid == 0) g_pg[bc] = gs;
}
__global__ void kv_p2() {
    int idx = blockIdx.x * blockDim.x + threadIdx.x;
    if (idx < Bv * Pv * Vv) {
        float* arr = blockIdx.y ? g_pks : g_pkc;
        int b = idx >> 10, pv = idx & 1023;
        float v[NCv];
#pragma unroll
        for (int c = 0; c < NCv; c++)
            v[c] = arr[((size_t)(b * NCv + c)) * 1024 + pv];
        float run = 0.f;
#pragma unroll
        for (int c = 0; c < NCv; c++) { float t = v[c]; v[c] = run; run += t; }
#pragma unroll
        for (int c = 0; c < NCv; c++)
            arr[((size_t)(b * NCv + c)) * 1024 + pv] = v[c];
    }
    if (blockIdx.x == 0 && blockIdx.y == 0 && idx < Bv) {
        float v[NCv];
#pragma unroll
        for (int c = 0; c < NCv; c++) v[c] = g_pg[(size_t)idx * NCv + c];
        float run = 0.f;
#pragma unroll
        for (int c = 0; c < NCv; c++) { float t = v[c]; v[c] = run; run += t; }
#pragma unroll
        for (int c = 0; c < NCv; c++) g_pg[(size_t)idx * NCv + c] = v[c];
    }
}
// fused: scan + retrieval + kv_out, 8-token rounds
__global__ void __launch_bounds__(256) kv_p3(
    const float* __restrict__ w_kv, const float* __restrict__ b_kv)
{
    __shared__ float s_csp[8][128], s_ssp[8][128], s_cqp[8][128], s_sqp[8][128];
    __shared__ float s_gv[8][8], s_gate[8], s_kvr[8][8];
    __shared__ float s_wkv[8 * 512];
    __shared__ float s_bkv[512];
    int bc = blockIdx.x; int b = bc >> NC_SH, c = bc & NC_MASK;
    int tid = threadIdx.x, w = tid >> 5, l = tid & 31;
    int mbase = b * Lv + c * LCv;
    for (int i = tid; i < 8 * 512; i += 256) s_wkv[i] = w_kv[i];
    for (int i = tid; i < 512; i += 256) s_bkv[i] = b_kv[i];
    float aC[4], aS[4];
#pragma unroll
    for (int j = 0; j < 4; j++) {
        size_t o = (size_t)bc * 1024 + (size_t)(4 * l + j) * 8 + w;
        aC[j] = g_pkc[o]; aS[j] = g_pks[o];
    }
    float gsum = g_pg[bc];
    for (int r0 = 0; r0 < LCv; r0 += 8) {
#pragma unroll
        for (int e = tid; e < 1024; e += 256) {
            int i = e >> 7, p = e & 127;
            size_t mm = (size_t)(mbase + r0 + i) * 128 + p;
            s_csp[i][p] = g_csp[mm];
            s_ssp[i][p] = g_ssp[mm];
            s_cqp[i][p] = g_cqp[mm];
            s_sqp[i][p] = g_sqp[mm];
        }
        if (tid < 64) s_gv[tid >> 3][tid & 7] = g_gv[(size_t)(mbase + r0 + (tid >> 3)) * 8 + (tid & 7)];
        if (tid < 8) s_gate[tid] = g_gate[mbase + r0 + tid];
        __syncthreads();
#pragma unroll
        for (int i = 0; i < 8; i++) {
            float gvv = s_gv[i][w];
            float4 cv = ((const float4*)s_csp[i])[l];
            float4 sv = ((const float4*)s_ssp[i])[l];
            float4 cq = ((const float4*)s_cqp[i])[l];
            float4 sq = ((const float4*)s_sqp[i])[l];
            aC[0] += cv.x * gvv; aS[0] += sv.x * gvv;
            aC[1] += cv.y * gvv; aS[1] += sv.y * gvv;
            aC[2] += cv.z * gvv; aS[2] += sv.z * gvv;
            aC[3] += cv.w * gvv; aS[3] += sv.w * gvv;
            float pr = cq.x * aC[0] + sq.x * aS[0]
                     + cq.y * aC[1] + sq.y * aS[1]
                     + cq.z * aC[2] + sq.z * aS[2]
                     + cq.w * aC[3] + sq.w * aS[3];
#pragma unroll
            for (int o = 16; o; o >>= 1)
                pr += __shfl_xor_sync(0xffffffffu, pr, o);
            gsum += s_gate[i];
            if (l == 0)
                s_kvr[i][w] = pr * rsqrtf(fmaxf(gsum, 1.0f)) * INV_SQRT_P;
        }
        __syncthreads();
        // kv_out for 8 tokens: 4096 outputs / 256 thr = 16 each
#pragma unroll
        for (int k = 0; k < 16; k++) {
            int idx = tid + k * 256;
            int tok = idx >> 9, n = idx & 511;
            float o = s_bkv[n];
#pragma unroll
            for (int v = 0; v < 8; v++)
                o += s_kvr[tok][v] * s_wkv[v * 512 + n];
            g_ccat[(size_t)(mbase + r0 + tok) * 1024 + 512 + n] = o;
        }
        __syncthreads();
    }
}

// ================= LayerNorm =================
__global__ void __launch_bounds__(256) ln_kernel(
    const float* __restrict__ lng, const float* __restrict__ lnb)
{
    int m = blockIdx.x, tid = threadIdx.x;
    const float4* row = (const float4*)(g_ccat + (size_t)m * 1024);
    float4 val = row[tid];
    float s = val.x + val.y + val.z + val.w;
    float q = val.x * val.x + val.y * val.y + val.z * val.z + val.w * val.w;
#pragma unroll
    for (int o = 16; o; o >>= 1) {
        s += __shfl_xor_sync(0xffffffffu, s, o);
        q += __shfl_xor_sync(0xffffffffu, q, o);
    }
    __shared__ float ss[8], sq[8];
    __shared__ float smu, srs;
    if ((tid & 31) == 0) { ss[tid >> 5] = s; sq[tid >> 5] = q; }
    __syncthreads();
    if (tid == 0) {
        float S = 0.f, Q = 0.f;
#pragma unroll
        for (int w = 0; w < 8; w++) { S += ss[w]; Q += sq[w]; }
        float mu = S * (1.f / 1024.f);
        float var = Q * (1.f / 1024.f) - mu * mu;
        smu = mu; srs = rsqrtf(var + 1e-5f);
    }
    __syncthreads();
    float mu = smu, rs = srs;
    float4 g4 = ((const float4*)lng)[tid];
    float4 b4 = ((const float4*)lnb)[tid];
    float4 o;
    o.x = (val.x - mu) * rs * g4.x + b4.x;
    o.y = (val.y - mu) * rs * g4.y + b4.y;
    o.z = (val.z - mu) * rs * g4.z + b4.z;
    o.w = (val.w - mu) * rs * g4.w + b4.w;
    ((float4*)(g_ln + (size_t)m * 1024))[tid] = o;
}

// ================= launch =================
extern "C" void kernel_launch(void* const* d_in, const int* in_sizes, int n_in,
                              void* d_out, int out_size)
{
    const float* x    = (const float*)d_in[0];
    const float* pos  = (const float*)d_in[1];
    const float* ms   = (const float*)d_in[2];
    const float* w_v  = (const float*)d_in[3];
    const float* b_v  = (const float*)d_in[4];
    const float* w_o  = (const float*)d_in[5];
    const float* b_o  = (const float*)d_in[6];
    const float* w_m  = (const float*)d_in[7];
    const float* b_m  = (const float*)d_in[8];
    const float* w_q  = (const float*)d_in[9];
    const float* b_q  = (const float*)d_in[10];
    const float* w_ke = (const float*)d_in[11];
    const float* b_ke = (const float*)d_in[12];
    const float* w_ve = (const float*)d_in[13];
    const float* b_ve = (const float*)d_in[14];
    const float* w_s1 = (const float*)d_in[15];
    const float* b_s1 = (const float*)d_in[16];
    const float* w_s2 = (const float*)d_in[17];
    const float* b_s2 = (const float*)d_in[18];
    const float* w_g  = (const float*)d_in[19];
    const float* b_g  = (const float*)d_in[20];
    const float* w_kv = (const float*)d_in[21];
    const float* b_kv = (const float*)d_in[22];
    const float* lng  = (const float*)d_in[23];
    const float* lnb  = (const float*)d_in[24];
    const float* w_t1 = (const float*)d_in[25];
    const float* b_t1 = (const float*)d_in[26];
    const float* w_t2 = (const float*)d_in[27];
    const float* b_t2 = (const float*)d_in[28];
    float* out = (float*)d_out;

    float *p_xcat, *p_v1, *p_mag, *p_qd, *p_s1g, *p_posret, *p_ccat, *p_ln,
          *p_h1, *p_wt, *p_cqp, *p_sqp, *p_csp, *p_ssp, *p_bcat;
    cudaGetSymbolAddress((void**)&p_xcat, g_xcat);
    cudaGetSymbolAddress((void**)&p_v1, g_v1);
    cudaGetSymbolAddress((void**)&p_mag, g_mag);
    cudaGetSymbolAddress((void**)&p_qd, g_qd);
    cudaGetSymbolAddress((void**)&p_s1g, g_s1g);
    cudaGetSymbolAddress((void**)&p_posret, g_posret);
    cudaGetSymbolAddress((void**)&p_ccat, g_ccat);
    cudaGetSymbolAddress((void**)&p_ln, g_ln);
    cudaGetSymbolAddress((void**)&p_h1, g_h1);
    cudaGetSymbolAddress((void**)&p_wt, g_wt);
    cudaGetSymbolAddress((void**)&p_cqp, g_cqp);
    cudaGetSymbolAddress((void**)&p_sqp, g_sqp);
    cudaGetSymbolAddress((void**)&p_csp, g_csp);
    cudaGetSymbolAddress((void**)&p_ssp, g_ssp);
    cudaGetSymbolAddress((void**)&p_bcat, g_bcat);

    float* wt_proj = p_wt + WT_PROJ;
    float* wt_o    = p_wt + WT_O;
    float* wt_s1   = p_wt + WT_S1;
    float* wt_s2   = p_wt + WT_S2;
    float* wt_t1   = p_wt + WT_T1;
    float* wt_t2   = p_wt + WT_T2;

    const int SMEM = 2 * STAGE_F * 4;  // 73728 B -> 2 CTAs/SM
    cudaFuncSetAttribute(mma_gemm, cudaFuncAttributeMaxDynamicSharedMemorySize, SMEM);

    TTable tt;
    tt.src[0] = w_v;  tt.dst[0] = wt_proj;              tt.K[0] = 512;  tt.N[0] = 512;
    tt.src[1] = w_m;  tt.dst[1] = wt_proj + 512 * 512;  tt.K[1] = 512;  tt.N[1] = 512;
    tt.src[2] = w_q;  tt.dst[2] = wt_proj + 1024 * 512; tt.K[2] = 512;  tt.N[2] = 512;
    tt.src[3] = w_ke; tt.dst[3] = wt_proj + 1536 * 512; tt.K[3] = 512;  tt.N[3] = 128;
    tt.src[4] = w_o;  tt.dst[4] = wt_o;                 tt.K[4] = 512;  tt.N[4] = 512;
    tt.src[5] = w_s1; tt.dst[5] = wt_s1;                tt.K[5] = 1024; tt.N[5] = 512;
    tt.src[6] = w_s2; tt.dst[6] = wt_s2;                tt.K[6] = 512;  tt.N[6] = 128;
    tt.src[7] = w_t1; tt.dst[7] = wt_t1;                tt.K[7] = 1024; tt.N[7] = 1024;
    tt.src[8] = w_t2; tt.dst[8] = wt_t2;                tt.K[8] = 1024; tt.N[8] = 512;
    int acc = 0;
    for (int i = 0; i < 9; i++) {
        tt.t0[i] = acc;
        acc += (tt.K[i] >> 5) * (tt.N[i] >> 5);
    }
    transpose_all<<<acc, 256>>>(tt);
    bias_concat<<<7, 256>>>(b_v, b_m, b_q, b_ke);

    dim3 tb(256);
    dim3 gScan(Bv * NCv, Dv / 128);

    ctx_p1<<<gScan, 128>>>(x);
    ctx_p2<<<(Bv * Dv + 255) / 256, 256>>>();
    ctx_p3<<<gScan, 128>>>(x);

    // merged projections: v | mag | qd | ke-sincos
    mma_gemm<<<dim3(13, 128), tb, SMEM>>>(x, wt_proj, p_bcat,
        p_v1, p_mag, p_qd, p_cqp, p_sqp, 512, 512, 6, ms);
    vg_kernel<<<Mv / 8, 256>>>(x, w_ve, b_ve, w_g, b_g);
    mma_gemm<<<dim3(4, 128), tb, SMEM>>>(p_xcat, wt_s1, b_s1,
        p_s1g, nullptr, nullptr, nullptr, nullptr, 1024, 512, 2, nullptr);
    mma_gemm<<<dim3(1, 128), tb, SMEM>>>(p_s1g, wt_s2, b_s2,
        p_csp, p_ssp, nullptr, nullptr, nullptr, 512, 128, 5, nullptr);

    // mem1 scan + pos_out
    mem1_p1<<<gScan, 128>>>(pos);
    mem1_p2<<<dim3((Bv * Dv + 255) / 256, 3), 256>>>();
    mem1_p3<<<gScan, 128>>>(pos);
    mma_gemm<<<dim3(4, 128), tb, SMEM>>>(p_posret, wt_o, b_o,
        p_ccat, nullptr, nullptr, nullptr, nullptr, 512, 1024, 0, nullptr);

    // kv scan + retrieval + fused kv_out (chunked)
    kv_p1<<<Bv * NCv, 256>>>();
    kv_p2<<<dim3((Bv * Pv * Vv + 255) / 256, 2), 256>>>();
    kv_p3<<<Bv * NCv, 256>>>(w_kv, b_kv);

    // LN + output MLP + residual
    ln_kernel<<<Mv, 256>>>(lng, lnb);
    mma_gemm<<<dim3(8, 128), tb, SMEM>>>(p_ln, wt_t1, b_t1,
        p_h1, nullptr, nullptr, nullptr, nullptr, 1024, 1024, 2, nullptr);
    mma_gemm<<<dim3(4, 128), tb, SMEM>>>(p_h1, wt_t2, b_t2,
        out, nullptr, nullptr, nullptr, nullptr, 1024, 512, 4, x);
}

// round 12
// speedup vs baseline: 1.6917x; 1.3048x over previous
#include <cuda_runtime.h>
#include <cuda_fp16.h>
#include <math.h>
#include <stdint.h>

#define Bv 4
#define Lv 4096
#define Dv 512
#define Pv 128
#define Vv 8
#define Mv (Bv*Lv)          // 16384
#define NCv 64
#define NC_SH 6
#define NC_MASK 63
#define LCv (Lv/NCv)        // 64
#define PI_F 3.14159265358979323846f
#define INV_SQRT_D 0.044194173824159216f
#define INV_SQRT_P 0.08838834764831845f

// ================= helpers =================
__device__ __forceinline__ uint32_t smem_u32(const void* p) {
    uint32_t a;
    asm("{ .reg .u64 t; cvta.to.shared.u64 t, %1; cvt.u32.u64 %0, t; }" : "=r"(a) : "l"(p));
    return a;
}
__device__ __forceinline__ void cp16(uint32_t s, const void* g) {
    asm volatile("cp.async.cg.shared.global [%0], [%1], 16;" :: "r"(s), "l"(g) : "memory");
}
#define CP_COMMIT() asm volatile("cp.async.commit_group;" ::: "memory")
#define CP_WAIT1()  asm volatile("cp.async.wait_group 1;" ::: "memory")
#define CP_WAIT0()  asm volatile("cp.async.wait_group 0;" ::: "memory")

__device__ __forceinline__ void mma_f16(float* c,
    uint32_t a0, uint32_t a1, uint32_t a2, uint32_t a3,
    uint32_t b0, uint32_t b1)
{
    asm volatile(
        "mma.sync.aligned.m16n8k16.row.col.f32.f16.f16.f32 "
        "{%0,%1,%2,%3}, {%4,%5,%6,%7}, {%8,%9}, {%0,%1,%2,%3};"
        : "+f"(c[0]), "+f"(c[1]), "+f"(c[2]), "+f"(c[3])
        : "r"(a0), "r"(a1), "r"(a2), "r"(a3), "r"(b0), "r"(b1));
}
__device__ __forceinline__ void ldmx4(uint32_t* r, uint32_t addr) {
    asm volatile(
        "ldmatrix.sync.aligned.m8n8.x4.shared.b16 {%0,%1,%2,%3}, [%4];"
        : "=r"(r[0]), "=r"(r[1]), "=r"(r[2]), "=r"(r[3]) : "r"(addr));
}

// ================= scratch =================
__device__ float g_v1[(size_t)Mv*512];
__device__ float g_mag[(size_t)Mv*512];
__device__ float g_qd[(size_t)Mv*512];
__device__ float g_cqp[(size_t)Mv*128], g_sqp[(size_t)Mv*128];
__device__ float g_csp[(size_t)Mv*128], g_ssp[(size_t)Mv*128];
__device__ float g_gv[(size_t)Mv*8], g_gate[Mv];
__device__ float g_ccat[(size_t)Mv*1024];
__device__ float g_bcat[1664];
__device__ float g_pctx[Bv*NCv*Dv];
__device__ float g_pmc[Bv*NCv*Dv], g_pms[Bv*NCv*Dv], g_pmm[Bv*NCv*Dv];
__device__ float g_pkc[Bv*NCv*Pv*Vv], g_pks[Bv*NCv*Pv*Vv], g_pg[Bv*NCv];
// fp16 GEMM operands
__device__ __half g_wth[3276800];
__device__ __half g_xcath[(size_t)Mv*1024];
__device__ __half g_s1gh[(size_t)Mv*512];
__device__ __half g_posreth[(size_t)Mv*512];
__device__ __half g_lnh[(size_t)Mv*1024];
__device__ __half g_h1h[(size_t)Mv*1024];

// arena offsets (halves)
#define WT_PROJ 0
#define WT_O    851968
#define WT_S1   1114112
#define WT_S2   1638400
#define WT_T1   1703936
#define WT_T2   2752512

// ================= batched transpose -> fp16 =================
struct TTable {
    const float* src[9];
    __half* dst[9];
    int K[9], N[9], t0[9];
};
__global__ void __launch_bounds__(256) transpose_all(TTable tt) {
    __shared__ float t[32][33];
    int bid = blockIdx.x;
    int w = 8;
#pragma unroll
    for (int i = 8; i >= 0; i--) if (bid >= tt.t0[i]) { w = i; break; }
    int tl = bid - tt.t0[w];
    int K = tt.K[w], N = tt.N[w];
    int tilesK = K >> 5;
    int k0 = (tl % tilesK) * 32, n0 = (tl / tilesK) * 32;
    const float* W = tt.src[w];
    __half* WT = tt.dst[w];
    int tx = threadIdx.x & 31, ty = threadIdx.x >> 5;
#pragma unroll
    for (int i = ty; i < 32; i += 8) t[i][tx] = W[(size_t)(k0 + i) * N + n0 + tx];
    __syncthreads();
#pragma unroll
    for (int i = ty; i < 32; i += 8)
        WT[(size_t)(n0 + i) * K + k0 + tx] = __float2half_rn(t[tx][i]);
}

// ================= bias concat =================
__global__ void bias_concat(const float* b_v, const float* b_m,
                            const float* b_q, const float* b_ke) {
    int i = blockIdx.x * blockDim.x + threadIdx.x;
    if (i < 512)        g_bcat[i] = b_v[i];
    else if (i < 1024)  g_bcat[i] = b_m[i - 512];
    else if (i < 1536)  g_bcat[i] = b_q[i - 1024];
    else if (i < 1664)  g_bcat[i] = b_ke[i - 1536];
}

// ================= fp16 mma.sync GEMM (128x128 tile, 2-stage, 2 CTAs/SM) =================
// epi: 0 none, 2 exact gelu, 4 +eptr residual, 5 sincos(tanh*PI)->C,C2,
//      6 merged-proj (v1|mag|qd|ke-sincos). ohalf: write C as __half.
#define LDA_H 40
#define STAGE_H (256 * LDA_H)   // halves per stage (A 128 rows + B 128 rows)
__global__ void __launch_bounds__(256, 2) mma_gemm(
    const __half* __restrict__ A, const __half* __restrict__ WT,
    const float* __restrict__ bias,
    float* __restrict__ C, float* __restrict__ C2, float* __restrict__ C3,
    float* __restrict__ C4, float* __restrict__ C5,
    int K, int lda, int ldc, int epi, int ohalf, const float* __restrict__ eptr)
{
    extern __shared__ __half smh[];
    const int tid = threadIdx.x, wid = tid >> 5, lane = tid & 31;
    const int warp_m = wid & 3, warp_n = wid >> 2;   // 4 x 2
    const int n0 = blockIdx.x * 128, m0 = blockIdx.y * 128;
    const int NK = K >> 5;
    const int lq = lane >> 2, lr = lane & 3;

    const int g = lane >> 3, r = lane & 7;
    // A frag: row = warp_m*32 + mi*16 + (g&1)*8 + r ; k-half-off = (g>>1)*8
    const uint32_t aoff = ((uint32_t)((warp_m * 32 + (g & 1) * 8 + r) * LDA_H
                           + (g >> 1) * 8)) * 2u;
    // B frag: n-row = warp_n*64 + jp*16 + (g>>1)*8 + r ; k-half-off = (g&1)*8
    const uint32_t boff = ((uint32_t)((warp_n * 64 + (g >> 1) * 8 + r) * LDA_H
                           + (g & 1) * 8)) * 2u;

    const uint32_t sbase = smem_u32(smh);

    float c[2][8][4];
#pragma unroll
    for (int mi = 0; mi < 2; mi++)
#pragma unroll
        for (int j = 0; j < 8; j++)
#pragma unroll
            for (int q = 0; q < 4; q++) c[mi][j][q] = 0.f;

    auto load_tile = [&](int kt, int buf) {
        __half* dst = smh + buf * STAGE_H;
        // A: 128 rows x 32 halves = 512 cp16 -> 2/thread
#pragma unroll
        for (int i = 0; i < 2; i++) {
            int idx = tid + i * 256;
            int row = idx >> 2, cq = idx & 3;
            cp16(smem_u32(dst + row * LDA_H + cq * 8),
                 A + (size_t)(m0 + row) * lda + kt * 32 + cq * 8);
        }
        // B
#pragma unroll
        for (int i = 0; i < 2; i++) {
            int idx = tid + i * 256;
            int row = idx >> 2, cq = idx & 3;
            cp16(smem_u32(dst + 128 * LDA_H + row * LDA_H + cq * 8),
                 WT + (size_t)(n0 + row) * K + kt * 32 + cq * 8);
        }
        CP_COMMIT();
    };

    load_tile(0, 0);

    for (int kt = 0; kt < NK; kt++) {
        int buf = kt & 1;
        if (kt + 1 < NK) load_tile(kt + 1, buf ^ 1);
        if (kt + 1 < NK) { CP_WAIT1(); } else { CP_WAIT0(); }
        __syncthreads();

        const uint32_t aBase = sbase + (uint32_t)(buf * STAGE_H) * 2u;
        const uint32_t bBase = aBase + 128u * LDA_H * 2u;
#pragma unroll
        for (int ks = 0; ks < 2; ks++) {
            uint32_t kbb = (uint32_t)ks * 32u;   // 16 halves = 32 bytes
            uint32_t a[2][4];
            ldmx4(a[0], aBase + aoff + kbb);
            ldmx4(a[1], aBase + aoff + 16u * LDA_H * 2u + kbb);
#pragma unroll
            for (int jp = 0; jp < 4; jp++) {
                uint32_t bR[4];
                ldmx4(bR, bBase + boff + (uint32_t)jp * 16u * LDA_H * 2u + kbb);
                int j0 = jp * 2;
                mma_f16(c[0][j0], a[0][0], a[0][1], a[0][2], a[0][3], bR[0], bR[1]);
                mma_f16(c[1][j0], a[1][0], a[1][1], a[1][2], a[1][3], bR[0], bR[1]);
                mma_f16(c[0][j0 + 1], a[0][0], a[0][1], a[0][2], a[0][3], bR[2], bR[3]);
                mma_f16(c[1][j0 + 1], a[1][0], a[1][1], a[1][2], a[1][3], bR[2], bR[3]);
            }
        }
        __syncthreads();
    }

    // ---------------- epilogue ----------------
    float scale1 = (epi == 6) ? fabsf(*eptr) : 0.f;
    int seg = n0 >> 9;
#pragma unroll
    for (int mi = 0; mi < 2; mi++) {
#pragma unroll
        for (int j = 0; j < 8; j++) {
            int gm = m0 + warp_m * 32 + mi * 16 + lq;
            int gn = n0 + warp_n * 64 + j * 8 + lr * 2;
            float b0 = bias[gn], b1 = bias[gn + 1];
#pragma unroll
            for (int h = 0; h < 2; h++) {
                int gmr = gm + h * 8;
                float v0 = c[mi][j][h * 2 + 0] + b0;
                float v1 = c[mi][j][h * 2 + 1] + b1;
                if (epi == 6) {
                    if (seg == 0) {
                        C[(size_t)gmr * 512 + gn] = v0;
                        C[(size_t)gmr * 512 + gn + 1] = v1;
                    } else if (seg == 1) {
                        size_t oo = (size_t)gmr * 512 + gn - 512;
                        C2[oo]     = scale1 / (1.f + expf(-v0));
                        C2[oo + 1] = scale1 / (1.f + expf(-v1));
                    } else if (seg == 2) {
                        size_t oo = (size_t)gmr * 512 + gn - 1024;
                        C3[oo] = v0; C3[oo + 1] = v1;
                    } else {
                        size_t oo = (size_t)gmr * 128 + gn - 1536;
                        float t0 = tanhf(v0) * PI_F, t1 = tanhf(v1) * PI_F;
                        float s0, cc0, s1, cc1;
                        sincosf(t0, &s0, &cc0);
                        sincosf(t1, &s1, &cc1);
                        C4[oo] = cc0; C4[oo + 1] = cc1;
                        C5[oo] = s0;  C5[oo + 1] = s1;
                    }
                    continue;
                }
                size_t oo = (size_t)gmr * ldc + gn;
                if (epi == 2) {
                    v0 = 0.5f * v0 * (1.f + erff(v0 * 0.70710678118654752f));
                    v1 = 0.5f * v1 * (1.f + erff(v1 * 0.70710678118654752f));
                } else if (epi == 4) {
                    v0 += eptr[oo];
                    v1 += eptr[oo + 1];
                } else if (epi == 5) {
                    float t0 = tanhf(v0) * PI_F, t1 = tanhf(v1) * PI_F;
                    float s0, c0, s1, c1;
                    sincosf(t0, &s0, &c0);
                    sincosf(t1, &s1, &c1);
                    C[oo] = c0; C[oo + 1] = c1;
                    C2[oo] = s0; C2[oo + 1] = s1;
                    continue;
                }
                if (ohalf) {
                    __half* Ch = (__half*)C;
                    Ch[oo] = __float2half_rn(v0);
                    Ch[oo + 1] = __float2half_rn(v1);
                } else {
                    C[oo] = v0; C[oo + 1] = v1;
                }
            }
        }
    }
}

// ================= context_avg scan =================
__global__ void ctx_p1(const float* __restrict__ x) {
    int bc = blockIdx.x; int b = bc >> NC_SH, c = bc & NC_MASK;
    int d = blockIdx.y * 128 + threadIdx.x;
    const float* xp = x + ((size_t)(b * Lv + c * LCv)) * Dv + d;
    float s0 = 0.f, s1 = 0.f, s2 = 0.f, s3 = 0.f;
#pragma unroll 4
    for (int i = 0; i < LCv; i += 4) {
        s0 += xp[(size_t)i * Dv];
        s1 += xp[(size_t)(i + 1) * Dv];
        s2 += xp[(size_t)(i + 2) * Dv];
        s3 += xp[(size_t)(i + 3) * Dv];
    }
    g_pctx[(size_t)bc * Dv + d] = (s0 + s1) + (s2 + s3);
}
__global__ void ctx_p2() {
    int idx = blockIdx.x * blockDim.x + threadIdx.x;
    if (idx >= Bv * Dv) return;
    int b = idx / Dv, d = idx % Dv;
    float v[NCv];
#pragma unroll
    for (int c = 0; c < NCv; c++)
        v[c] = g_pctx[((size_t)(b * NCv + c)) * Dv + d];
    float run = 0.f;
#pragma unroll
    for (int c = 0; c < NCv; c++) { float t = v[c]; v[c] = run; run += t; }
#pragma unroll
    for (int c = 0; c < NCv; c++)
        g_pctx[((size_t)(b * NCv + c)) * Dv + d] = v[c];
}
__global__ void ctx_p3(const float* __restrict__ x) {
    int bc = blockIdx.x; int b = bc >> NC_SH, c = bc & NC_MASK;
    int d = blockIdx.y * 128 + threadIdx.x;
    const float* xp = x + ((size_t)(b * Lv + c * LCv)) * Dv + d;
    float s = g_pctx[(size_t)bc * Dv + d];
    for (int i = 0; i < LCv; i++) {
        int l = c * LCv + i;
        float xv = xp[(size_t)i * Dv];
        s += xv;
        size_t row = (size_t)(b * Lv + l);
        g_xcath[row * 1024 + d] = __float2half_rn(xv);
        g_xcath[row * 1024 + 512 + d] = __float2half_rn(s / (float)(l + 1));
    }
}

// ================= values*gate =================
__global__ void __launch_bounds__(256) vg_kernel(
    const float* __restrict__ x, const float* __restrict__ w_ve,
    const float* __restrict__ b_ve, const float* __restrict__ w_g,
    const float* __restrict__ b_g)
{
    __shared__ float sw[8 * 512];
    __shared__ float sg[512];
    int tid = threadIdx.x;
    for (int idx = tid; idx < 512 * 8; idx += 256) {
        int k = idx >> 3, v = idx & 7;
        sw[v * 512 + k] = w_ve[idx];
    }
    for (int idx = tid; idx < 512; idx += 256) sg[idx] = w_g[idx];
    __syncthreads();
    int lane = tid & 31, w = tid >> 5;
    int m = blockIdx.x * 8 + w;
    const float* xr = x + (size_t)m * 512;
    float acc[8] = {0, 0, 0, 0, 0, 0, 0, 0}, ag = 0.f;
    for (int j = 0; j < 16; j++) {
        int k = lane + 32 * j;
        float xk = xr[k];
#pragma unroll
        for (int v = 0; v < 8; v++) acc[v] += xk * sw[v * 512 + k];
        ag += xk * sg[k];
    }
#pragma unroll
    for (int o = 16; o; o >>= 1) {
#pragma unroll
        for (int v = 0; v < 8; v++) acc[v] += __shfl_xor_sync(0xffffffffu, acc[v], o);
        ag += __shfl_xor_sync(0xffffffffu, ag, o);
    }
    if (lane == 0) {
        float gate = 1.f / (1.f + expf(-(ag + b_g[0])));
        g_gate[m] = gate;
#pragma unroll
        for (int v = 0; v < 8; v++) g_gv[(size_t)m * 8 + v] = (acc[v] + b_ve[v]) * gate;
    }
}

// ================= mem1 scan + fused pos_ret =================
__global__ void mem1_p1(const float* __restrict__ pos) {
    int bc = blockIdx.x; int b = bc >> NC_SH, c = bc & NC_MASK;
    int d = blockIdx.y * 128 + threadIdx.x;
    size_t base = ((size_t)(b * Lv + c * LCv)) * Dv + d;
    float sc = 0.f, ss = 0.f, sm = 0.f;
    for (int i = 0; i < LCv; i++) {
        int lg = c * LCv + i;
        float mag = g_mag[base + (size_t)i * Dv];
        float v1  = g_v1[base + (size_t)i * Dv];
        float w = mag * v1;
        float sphi, cphi;
        sincosf(pos[(size_t)lg * Dv + d], &sphi, &cphi);
        sc += w * cphi;
        ss += w * sphi;
        sm += mag;
    }
    size_t o = (size_t)bc * Dv + d;
    g_pmc[o] = sc; g_pms[o] = ss; g_pmm[o] = sm;
}
__global__ void mem1_p2() {
    int idx = blockIdx.x * blockDim.x + threadIdx.x;
    if (idx >= Bv * Dv) return;
    int sel = blockIdx.y;
    float* arr = (sel == 0) ? g_pmc : ((sel == 1) ? g_pms : g_pmm);
    int b = idx / Dv, d = idx % Dv;
    float v[NCv];
#pragma unroll
    for (int c = 0; c < NCv; c++)
        v[c] = arr[((size_t)(b * NCv + c)) * Dv + d];
    float run = 0.f;
#pragma unroll
    for (int c = 0; c < NCv; c++) { float t = v[c]; v[c] = run; run += t; }
#pragma unroll
    for (int c = 0; c < NCv; c++)
        arr[((size_t)(b * NCv + c)) * Dv + d] = v[c];
}
__global__ void mem1_p3(const float* __restrict__ pos) {
    int bc = blockIdx.x; int b = bc >> NC_SH, c = bc & NC_MASK;
    int d = blockIdx.y * 128 + threadIdx.x;
    size_t base = ((size_t)(b * Lv + c * LCv)) * Dv + d;
    size_t po = (size_t)bc * Dv + d;
    float sc = g_pmc[po], ss = g_pms[po], sm = g_pmm[po];
    for (int i = 0; i < LCv; i++) {
        int lg = c * LCv + i;
        float mag = g_mag[base + (size_t)i * Dv];
        float v1  = g_v1[base + (size_t)i * Dv];
        float w = mag * v1;
        float pp = pos[(size_t)lg * Dv + d];
        float sphi, cphi;
        sincosf(pp, &sphi, &cphi);
        sc += w * cphi;
        ss += w * sphi;
        sm += mag;
        float ph = pp + g_qd[base + (size_t)i * Dv];
        float sq, cq;
        sincosf(ph, &sq, &cq);
        g_posreth[base + (size_t)i * Dv] = __float2half_rn(
            (sc * cq + ss * sq) * rsqrtf(sm + 1e-8f) * INV_SQRT_D);
    }
}

// ================= kv phasor scan: 8-token chunked, warp-per-v =================
__global__ void __launch_bounds__(256) kv_p1() {
    __shared__ float s_csp[8][128], s_ssp[8][128];
    __shared__ float s_gv[8][8], s_gate[8];
    int bc = blockIdx.x; int b = bc >> NC_SH, c = bc & NC_MASK;
    int tid = threadIdx.x, w = tid >> 5, l = tid & 31;
    int mbase = b * Lv + c * LCv;
    float aC[4] = {0, 0, 0, 0}, aS[4] = {0, 0, 0, 0};
    float gs = 0.f;
    for (int r0 = 0; r0 < LCv; r0 += 8) {
#pragma unroll
        for (int e = tid; e < 1024; e += 256) {
            int i = e >> 7, p = e & 127;
            size_t mm = (size_t)(mbase + r0 + i) * 128 + p;
            s_csp[i][p] = g_csp[mm];
            s_ssp[i][p] = g_ssp[mm];
        }
        if (tid < 64) s_gv[tid >> 3][tid & 7] = g_gv[(size_t)(mbase + r0 + (tid >> 3)) * 8 + (tid & 7)];
        if (tid < 8) s_gate[tid] = g_gate[mbase + r0 + tid];
        __syncthreads();
#pragma unroll
        for (int i = 0; i < 8; i++) {
            float gvv = s_gv[i][w];
            float4 cv = ((const float4*)s_csp[i])[l];
            float4 sv = ((const float4*)s_ssp[i])[l];
            aC[0] += cv.x * gvv; aC[1] += cv.y * gvv;
            aC[2] += cv.z * gvv; aC[3] += cv.w * gvv;
            aS[0] += sv.x * gvv; aS[1] += sv.y * gvv;
            aS[2] += sv.z * gvv; aS[3] += sv.w * gvv;
            gs += s_gate[i];
        }
        __syncthreads();
    }
#pragma unroll
    for (int j = 0; j < 4; j++) {
        size_t o = (size_t)bc * 1024 + (size_t)(4 * l + j) * 8 + w;
        g_pkc[o] = aC[j]; g_pks[o] = aS[j];
    }
    if (tid == 0) g_pg[bc] = gs;
}
__global__ void kv_p2() {
    int idx = blockIdx.x * blockDim.x + threadIdx.x;
    if (idx < Bv * Pv * Vv) {
        float* arr = blockIdx.y ? g_pks : g_pkc;
        int b = idx >> 10, pv = idx & 1023;
        float v[NCv];
#pragma unroll
        for (int c = 0; c < NCv; c++)
            v[c] = arr[((size_t)(b * NCv + c)) * 1024 + pv];
        float run = 0.f;
#pragma unroll
        for (int c = 0; c < NCv; c++) { float t = v[c]; v[c] = run; run += t; }
#pragma unroll
        for (int c = 0; c < NCv; c++)
            arr[((size_t)(b * NCv + c)) * 1024 + pv] = v[c];
    }
    if (blockIdx.x == 0 && blockIdx.y == 0 && idx < Bv) {
        float v[NCv];
#pragma unroll
        for (int c = 0; c < NCv; c++) v[c] = g_pg[(size_t)idx * NCv + c];
        float run = 0.f;
#pragma unroll
        for (int c = 0; c < NCv; c++) { float t = v[c]; v[c] = run; run += t; }
#pragma unroll
        for (int c = 0; c < NCv; c++) g_pg[(size_t)idx * NCv + c] = v[c];
    }
}
__global__ void __launch_bounds__(256) kv_p3(
    const float* __restrict__ w_kv, const float* __restrict__ b_kv)
{
    __shared__ float s_csp[8][128], s_ssp[8][128], s_cqp[8][128], s_sqp[8][128];
    __shared__ float s_gv[8][8], s_gate[8], s_kvr[8][8];
    __shared__ float s_wkv[8 * 512];
    __shared__ float s_bkv[512];
    int bc = blockIdx.x; int b = bc >> NC_SH, c = bc & NC_MASK;
    int tid = threadIdx.x, w = tid >> 5, l = tid & 31;
    int mbase = b * Lv + c * LCv;
    for (int i = tid; i < 8 * 512; i += 256) s_wkv[i] = w_kv[i];
    for (int i = tid; i < 512; i += 256) s_bkv[i] = b_kv[i];
    float aC[4], aS[4];
#pragma unroll
    for (int j = 0; j < 4; j++) {
        size_t o = (size_t)bc * 1024 + (size_t)(4 * l + j) * 8 + w;
        aC[j] = g_pkc[o]; aS[j] = g_pks[o];
    }
    float gsum = g_pg[bc];
    for (int r0 = 0; r0 < LCv; r0 += 8) {
#pragma unroll
        for (int e = tid; e < 1024; e += 256) {
            int i = e >> 7, p = e & 127;
            size_t mm = (size_t)(mbase + r0 + i) * 128 + p;
            s_csp[i][p] = g_csp[mm];
            s_ssp[i][p] = g_ssp[mm];
            s_cqp[i][p] = g_cqp[mm];
            s_sqp[i][p] = g_sqp[mm];
        }
        if (tid < 64) s_gv[tid >> 3][tid & 7] = g_gv[(size_t)(mbase + r0 + (tid >> 3)) * 8 + (tid & 7)];
        if (tid < 8) s_gate[tid] = g_gate[mbase + r0 + tid];
        __syncthreads();
#pragma unroll
        for (int i = 0; i < 8; i++) {
            float gvv = s_gv[i][w];
            float4 cv = ((const float4*)s_csp[i])[l];
            float4 sv = ((const float4*)s_ssp[i])[l];
            float4 cq = ((const float4*)s_cqp[i])[l];
            float4 sq = ((const float4*)s_sqp[i])[l];
            aC[0] += cv.x * gvv; aS[0] += sv.x * gvv;
            aC[1] += cv.y * gvv; aS[1] += sv.y * gvv;
            aC[2] += cv.z * gvv; aS[2] += sv.z * gvv;
            aC[3] += cv.w * gvv; aS[3] += sv.w * gvv;
            float pr = cq.x * aC[0] + sq.x * aS[0]
                     + cq.y * aC[1] + sq.y * aS[1]
                     + cq.z * aC[2] + sq.z * aS[2]
                     + cq.w * aC[3] + sq.w * aS[3];
#pragma unroll
            for (int o = 16; o; o >>= 1)
                pr += __shfl_xor_sync(0xffffffffu, pr, o);
            gsum += s_gate[i];
            if (l == 0)
                s_kvr[i][w] = pr * rsqrtf(fmaxf(gsum, 1.0f)) * INV_SQRT_P;
        }
        __syncthreads();
#pragma unroll
        for (int k = 0; k < 16; k++) {
            int idx = tid + k * 256;
            int tok = idx >> 9, n = idx & 511;
            float o = s_bkv[n];
#pragma unroll
            for (int v = 0; v < 8; v++)
                o += s_kvr[tok][v] * s_wkv[v * 512 + n];
            g_ccat[(size_t)(mbase + r0 + tok) * 1024 + 512 + n] = o;
        }
        __syncthreads();
    }
}

// ================= LayerNorm -> fp16 =================
__global__ void __launch_bounds__(256) ln_kernel(
    const float* __restrict__ lng, const float* __restrict__ lnb)
{
    int m = blockIdx.x, tid = threadIdx.x;
    const float4* row = (const float4*)(g_ccat + (size_t)m * 1024);
    float4 val = row[tid];
    float s = val.x + val.y + val.z + val.w;
    float q = val.x * val.x + val.y * val.y + val.z * val.z + val.w * val.w;
#pragma unroll
    for (int o = 16; o; o >>= 1) {
        s += __shfl_xor_sync(0xffffffffu, s, o);
        q += __shfl_xor_sync(0xffffffffu, q, o);
    }
    __shared__ float ss[8], sq[8];
    __shared__ float smu, srs;
    if ((tid & 31) == 0) { ss[tid >> 5] = s; sq[tid >> 5] = q; }
    __syncthreads();
    if (tid == 0) {
        float S = 0.f, Q = 0.f;
#pragma unroll
        for (int w = 0; w < 8; w++) { S += ss[w]; Q += sq[w]; }
        float mu = S * (1.f / 1024.f);
        float var = Q * (1.f / 1024.f) - mu * mu;
        smu = mu; srs = rsqrtf(var + 1e-5f);
    }
    __syncthreads();
    float mu = smu, rs = srs;
    float4 g4 = ((const float4*)lng)[tid];
    float4 b4 = ((const float4*)lnb)[tid];
    __half2* oh = (__half2*)(g_lnh + (size_t)m * 1024);
    oh[tid * 2]     = __floats2half2_rn((val.x - mu) * rs * g4.x + b4.x,
                                        (val.y - mu) * rs * g4.y + b4.y);
    oh[tid * 2 + 1] = __floats2half2_rn((val.z - mu) * rs * g4.z + b4.z,
                                        (val.w - mu) * rs * g4.w + b4.w);
}

// ================= launch =================
extern "C" void kernel_launch(void* const* d_in, const int* in_sizes, int n_in,
                              void* d_out, int out_size)
{
    const float* x    = (const float*)d_in[0];
    const float* pos  = (const float*)d_in[1];
    const float* ms   = (const float*)d_in[2];
    const float* w_v  = (const float*)d_in[3];
    const float* b_v  = (const float*)d_in[4];
    const float* w_o  = (const float*)d_in[5];
    const float* b_o  = (const float*)d_in[6];
    const float* w_m  = (const float*)d_in[7];
    const float* b_m  = (const float*)d_in[8];
    const float* w_q  = (const float*)d_in[9];
    const float* b_q  = (const float*)d_in[10];
    const float* w_ke = (const float*)d_in[11];
    const float* b_ke = (const float*)d_in[12];
    const float* w_ve = (const float*)d_in[13];
    const float* b_ve = (const float*)d_in[14];
    const float* w_s1 = (const float*)d_in[15];
    const float* b_s1 = (const float*)d_in[16];
    const float* w_s2 = (const float*)d_in[17];
    const float* b_s2 = (const float*)d_in[18];
    const float* w_g  = (const float*)d_in[19];
    const float* b_g  = (const float*)d_in[20];
    const float* w_kv = (const float*)d_in[21];
    const float* b_kv = (const float*)d_in[22];
    const float* lng  = (const float*)d_in[23];
    const float* lnb  = (const float*)d_in[24];
    const float* w_t1 = (const float*)d_in[25];
    const float* b_t1 = (const float*)d_in[26];
    const float* w_t2 = (const float*)d_in[27];
    const float* b_t2 = (const float*)d_in[28];
    float* out = (float*)d_out;

    float *p_v1, *p_mag, *p_qd, *p_ccat, *p_cqp, *p_sqp, *p_csp, *p_ssp, *p_bcat;
    __half *p_wth, *p_xcath, *p_s1gh, *p_posreth, *p_lnh, *p_h1h;
    cudaGetSymbolAddress((void**)&p_v1, g_v1);
    cudaGetSymbolAddress((void**)&p_mag, g_mag);
    cudaGetSymbolAddress((void**)&p_qd, g_qd);
    cudaGetSymbolAddress((void**)&p_ccat, g_ccat);
    cudaGetSymbolAddress((void**)&p_cqp, g_cqp);
    cudaGetSymbolAddress((void**)&p_sqp, g_sqp);
    cudaGetSymbolAddress((void**)&p_csp, g_csp);
    cudaGetSymbolAddress((void**)&p_ssp, g_ssp);
    cudaGetSymbolAddress((void**)&p_bcat, g_bcat);
    cudaGetSymbolAddress((void**)&p_wth, g_wth);
    cudaGetSymbolAddress((void**)&p_xcath, g_xcath);
    cudaGetSymbolAddress((void**)&p_s1gh, g_s1gh);
    cudaGetSymbolAddress((void**)&p_posreth, g_posreth);
    cudaGetSymbolAddress((void**)&p_lnh, g_lnh);
    cudaGetSymbolAddress((void**)&p_h1h, g_h1h);

    __half* wt_proj = p_wth + WT_PROJ;
    __half* wt_o    = p_wth + WT_O;
    __half* wt_s1   = p_wth + WT_S1;
    __half* wt_s2   = p_wth + WT_S2;
    __half* wt_t1   = p_wth + WT_T1;
    __half* wt_t2   = p_wth + WT_T2;

    const int SMEM = 2 * STAGE_H * 2;  // 40960 B
    cudaFuncSetAttribute(mma_gemm, cudaFuncAttributeMaxDynamicSharedMemorySize, SMEM);

    TTable tt;
    tt.src[0] = w_v;  tt.dst[0] = wt_proj;              tt.K[0] = 512;  tt.N[0] = 512;
    tt.src[1] = w_m;  tt.dst[1] = wt_proj + 512 * 512;  tt.K[1] = 512;  tt.N[1] = 512;
    tt.src[2] = w_q;  tt.dst[2] = wt_proj + 1024 * 512; tt.K[2] = 512;  tt.N[2] = 512;
    tt.src[3] = w_ke; tt.dst[3] = wt_proj + 1536 * 512; tt.K[3] = 512;  tt.N[3] = 128;
    tt.src[4] = w_o;  tt.dst[4] = wt_o;                 tt.K[4] = 512;  tt.N[4] = 512;
    tt.src[5] = w_s1; tt.dst[5] = wt_s1;                tt.K[5] = 1024; tt.N[5] = 512;
    tt.src[6] = w_s2; tt.dst[6] = wt_s2;                tt.K[6] = 512;  tt.N[6] = 128;
    tt.src[7] = w_t1; tt.dst[7] = wt_t1;                tt.K[7] = 1024; tt.N[7] = 1024;
    tt.src[8] = w_t2; tt.dst[8] = wt_t2;                tt.K[8] = 1024; tt.N[8] = 512;
    int acc = 0;
    for (int i = 0; i < 9; i++) {
        tt.t0[i] = acc;
        acc += (tt.K[i] >> 5) * (tt.N[i] >> 5);
    }
    transpose_all<<<acc, 256>>>(tt);
    bias_concat<<<7, 256>>>(b_v, b_m, b_q, b_ke);

    dim3 tb(256);
    dim3 gScan(Bv * NCv, Dv / 128);

    ctx_p1<<<gScan, 128>>>(x);
    ctx_p2<<<(Bv * Dv + 255) / 256, 256>>>();
    ctx_p3<<<gScan, 128>>>(x);

    // merged projections: v | mag | qd | ke-sincos  (A = xcat[:, :512] = x)
    mma_gemm<<<dim3(13, 128), tb, SMEM>>>(p_xcath, wt_proj, p_bcat,
        p_v1, p_mag, p_qd, p_cqp, p_sqp, 512, 1024, 512, 6, 0, ms);
    vg_kernel<<<Mv / 8, 256>>>(x, w_ve, b_ve, w_g, b_g);
    mma_gemm<<<dim3(4, 128), tb, SMEM>>>(p_xcath, wt_s1, b_s1,
        (float*)p_s1gh, nullptr, nullptr, nullptr, nullptr, 1024, 1024, 512, 2, 1, nullptr);
    mma_gemm<<<dim3(1, 128), tb, SMEM>>>(p_s1gh, wt_s2, b_s2,
        p_csp, p_ssp, nullptr, nullptr, nullptr, 512, 512, 128, 5, 0, nullptr);

    // mem1 scan + pos_out
    mem1_p1<<<gScan, 128>>>(pos);
    mem1_p2<<<dim3((Bv * Dv + 255) / 256, 3), 256>>>();
    mem1_p3<<<gScan, 128>>>(pos);
    mma_gemm<<<dim3(4, 128), tb, SMEM>>>(p_posreth, wt_o, b_o,
        p_ccat, nullptr, nullptr, nullptr, nullptr, 512, 512, 1024, 0, 0, nullptr);

    // kv scan + retrieval + fused kv_out (chunked)
    kv_p1<<<Bv * NCv, 256>>>();
    kv_p2<<<dim3((Bv * Pv * Vv + 255) / 256, 2), 256>>>();
    kv_p3<<<Bv * NCv, 256>>>(w_kv, b_kv);

    // LN + output MLP + residual
    ln_kernel<<<Mv, 256>>>(lng, lnb);
    mma_gemm<<<dim3(8, 128), tb, SMEM>>>(p_lnh, wt_t1, b_t1,
        (float*)p_h1h, nullptr, nullptr, nullptr, nullptr, 1024, 1024, 1024, 2, 1, nullptr);
    mma_gemm<<<dim3(4, 128), tb, SMEM>>>(p_h1h, wt_t2, b_t2,
        out, nullptr, nullptr, nullptr, nullptr, 1024, 1024, 512, 4, 0, x);
}